// round 5
// baseline (speedup 1.0000x reference)
#include <cuda_runtime.h>
#include <cuda_bf16.h>
#include <cstdint>

#define N_NODES 100000
#define F 128
#define MAXE 1600000
#define TR 64             // rows per transform block
#define LDR 257           // padded k-stride for row-major input tile
#define SCAN_T 1024
#define CHUNK ((N_NODES + SCAN_T - 1) / SCAN_T)   // 98

// Scratch (allocation-free rule: __device__ globals)
__device__ float g_agg[N_NODES * F];   // scaled mean of neighbor features
__device__ int   g_cnt[N_NODES];       // degree (histogram)
__device__ int   g_cur[N_NODES];       // fill cursors
__device__ int   g_off[N_NODES];       // CSR offsets
__device__ int   g_csr[MAXE];          // CSR column (src) indices

// packed f32x2 FMA: acc = a*b + acc  (2 fp32 FMAs per issue slot)
#define FMA2(acc, a, b) \
    asm("fma.rn.f32x2 %0, %1, %2, %0;" : "+l"(acc) : "l"(a), "l"(b))
#define PACKDUP(p, f) do { unsigned _u = __float_as_uint(f); \
    asm("mov.b64 %0, {%1, %1};" : "=l"(p) : "r"(_u)); } while (0)

// ---------------------------------------------------------------------------
// A: zero the int arrays
// ---------------------------------------------------------------------------
__global__ void zero_kernel() {
    int idx = blockIdx.x * blockDim.x + threadIdx.x;
    int stride = gridDim.x * blockDim.x;
    for (int i = idx; i < N_NODES; i += stride) {
        g_cnt[i] = 0;
        g_cur[i] = 0;
    }
}

// ---------------------------------------------------------------------------
// B: degree histogram over dst indices (edge_index is int32)
// ---------------------------------------------------------------------------
__global__ void hist_kernel(const int* __restrict__ ei, int E) {
    int idx = blockIdx.x * blockDim.x + threadIdx.x;
    int stride = gridDim.x * blockDim.x;
    for (int e = idx; e < E; e += stride) {
        int d = ei[E + e];
        if ((unsigned)d < (unsigned)N_NODES) atomicAdd(&g_cnt[d], 1);
    }
}

// ---------------------------------------------------------------------------
// C: exclusive scan g_cnt -> g_off, single block (thread-serial chunks)
// ---------------------------------------------------------------------------
__global__ void scan_kernel() {
    __shared__ int s[SCAN_T];
    int tid = threadIdx.x;
    int base = tid * CHUNK;
    int hi = min(base + CHUNK, N_NODES);

    int sum = 0;
    for (int i = base; i < hi; i++) sum += g_cnt[i];
    s[tid] = sum;
    __syncthreads();
#pragma unroll
    for (int d = 1; d < SCAN_T; d <<= 1) {
        int t = (tid >= d) ? s[tid - d] : 0;
        __syncthreads();
        s[tid] += t;
        __syncthreads();
    }
    int run = s[tid] - sum;   // exclusive prefix of this chunk
    for (int i = base; i < hi; i++) {
        int c = g_cnt[i];
        g_off[i] = run;
        run += c;
    }
}

// ---------------------------------------------------------------------------
// D: CSR fill — csr[off[d] + cursor[d]++] = s
// ---------------------------------------------------------------------------
__global__ void fill_kernel(const int* __restrict__ ei, int E) {
    int idx = blockIdx.x * blockDim.x + threadIdx.x;
    int stride = gridDim.x * blockDim.x;
    for (int e = idx; e < E; e += stride) {
        int s = ei[e];
        int d = ei[E + e];
        if ((unsigned)s >= (unsigned)N_NODES ||
            (unsigned)d >= (unsigned)N_NODES) continue;
        int p = atomicAdd(&g_cur[d], 1);
        g_csr[g_off[d] + p] = s;
    }
}

// ---------------------------------------------------------------------------
// E: aggregate — one warp per dst node, gather + mean, no atomics
// ---------------------------------------------------------------------------
__global__ void aggregate_kernel(const float* __restrict__ x) {
    int gtid = blockIdx.x * blockDim.x + threadIdx.x;
    int w = gtid >> 5;
    int lane = gtid & 31;
    if (w >= N_NODES) return;
    int off = g_off[w];
    int deg = g_cnt[w];
    int end = off + deg;

    float4 accA = make_float4(0.f, 0.f, 0.f, 0.f);
    float4 accB = make_float4(0.f, 0.f, 0.f, 0.f);
    int i = off;
    for (; i + 8 <= end; i += 8) {
        int s0 = g_csr[i + 0], s1 = g_csr[i + 1];
        int s2 = g_csr[i + 2], s3 = g_csr[i + 3];
        int s4 = g_csr[i + 4], s5 = g_csr[i + 5];
        int s6 = g_csr[i + 6], s7 = g_csr[i + 7];
        float4 v0 = ((const float4*)(x + (long long)s0 * F))[lane];
        float4 v1 = ((const float4*)(x + (long long)s1 * F))[lane];
        float4 v2 = ((const float4*)(x + (long long)s2 * F))[lane];
        float4 v3 = ((const float4*)(x + (long long)s3 * F))[lane];
        float4 v4 = ((const float4*)(x + (long long)s4 * F))[lane];
        float4 v5 = ((const float4*)(x + (long long)s5 * F))[lane];
        float4 v6 = ((const float4*)(x + (long long)s6 * F))[lane];
        float4 v7 = ((const float4*)(x + (long long)s7 * F))[lane];
        accA.x += (v0.x + v1.x) + (v2.x + v3.x);
        accA.y += (v0.y + v1.y) + (v2.y + v3.y);
        accA.z += (v0.z + v1.z) + (v2.z + v3.z);
        accA.w += (v0.w + v1.w) + (v2.w + v3.w);
        accB.x += (v4.x + v5.x) + (v6.x + v7.x);
        accB.y += (v4.y + v5.y) + (v6.y + v7.y);
        accB.z += (v4.z + v5.z) + (v6.z + v7.z);
        accB.w += (v4.w + v5.w) + (v6.w + v7.w);
    }
    for (; i < end; i++) {
        int s = g_csr[i];
        float4 v = ((const float4*)(x + (long long)s * F))[lane];
        accA.x += v.x; accA.y += v.y; accA.z += v.z; accA.w += v.w;
    }
    float sc = 1.f / fmaxf((float)deg, 1.f);
    float4 o;
    o.x = (accA.x + accB.x) * sc;
    o.y = (accA.y + accB.y) * sc;
    o.z = (accA.z + accB.z) * sc;
    o.w = (accA.w + accB.w) * sc;
    ((float4*)(g_agg + (long long)w * F))[lane] = o;
}

// ---------------------------------------------------------------------------
// F: fused transform via packed f32x2 FMA.
//   out[i] = agg[i] @ W_l^T + 1{deg>0}*b_l + x[i] @ W_r^T
// in256 = [agg ; x] row-major in smem; W256 = [W_l ; W_r] transposed (Wt[k][c]).
// 64 rows/block, 4 rows x 8 cols per thread, accs as 4x4 f32x2 pairs.
// ---------------------------------------------------------------------------
__global__ void __launch_bounds__(256, 1)
transform_kernel(const float* __restrict__ x,
                 const float* __restrict__ W_l,
                 const float* __restrict__ b_l,
                 const float* __restrict__ W_r,
                 float* __restrict__ out) {
    extern __shared__ float sm[];
    float* Wt  = sm;                 // [256][128]
    float* inT = sm + 256 * 128;     // [TR][LDR] row-major (r, k)
    __shared__ float s_bias[128];
    __shared__ float s_dflag[TR];

    int tid = threadIdx.x;
    int row0 = blockIdx.x * TR;

    // Wt[k*128 + c] = W[c][k]
    for (int idx = tid; idx < 256 * 128; idx += 256) {
        int k = idx >> 7;
        int c = idx & 127;
        Wt[idx] = (k < 128) ? W_l[c * 128 + k] : W_r[c * 128 + (k - 128)];
    }
    if (tid < 128) s_bias[tid] = b_l[tid];
    if (tid < TR) {
        int r = row0 + tid;
        int d = (r < N_NODES) ? g_cnt[r] : 0;
        s_dflag[tid] = (d > 0) ? 1.f : 0.f;
    }

    // Row-major input tile: inT[r*LDR + k] (agg in k[0,128), x in k[128,256))
    // Consecutive tid -> consecutive k: coalesced global, conflict-free smem.
    for (int idx = tid; idx < TR * 128; idx += 256) {
        int r = idx >> 7;
        int k = idx & 127;
        int row = row0 + r;
        float av = 0.f, xv = 0.f;
        if (row < N_NODES) {
            av = g_agg[(long long)row * 128 + k];   // already scaled
            xv = x[(long long)row * 128 + k];
        }
        inT[r * LDR + k] = av;
        inT[r * LDR + 128 + k] = xv;
    }
    __syncthreads();

    int cg = tid & 15;   // cols cg*8 .. cg*8+7
    int rg = tid >> 4;   // rows rg*4 .. rg*4+3
    unsigned long long acc[4][4];
#pragma unroll
    for (int i = 0; i < 4; i++)
#pragma unroll
        for (int j = 0; j < 4; j++) acc[i][j] = 0ULL;

    const float* aB = inT + rg * 4 * LDR;
    const float* bB = Wt + cg * 8;

#pragma unroll 4
    for (int k = 0; k < 256; k++) {
        float a0 = aB[0 * LDR + k];
        float a1 = aB[1 * LDR + k];
        float a2 = aB[2 * LDR + k];
        float a3 = aB[3 * LDR + k];
        unsigned long long a0p, a1p, a2p, a3p;
        PACKDUP(a0p, a0); PACKDUP(a1p, a1);
        PACKDUP(a2p, a2); PACKDUP(a3p, a3);
        ulonglong2 b01 = *(const ulonglong2*)(bB + k * 128);      // cols 0-3
        ulonglong2 b23 = *(const ulonglong2*)(bB + k * 128 + 4);  // cols 4-7
        FMA2(acc[0][0], a0p, b01.x); FMA2(acc[0][1], a0p, b01.y);
        FMA2(acc[0][2], a0p, b23.x); FMA2(acc[0][3], a0p, b23.y);
        FMA2(acc[1][0], a1p, b01.x); FMA2(acc[1][1], a1p, b01.y);
        FMA2(acc[1][2], a1p, b23.x); FMA2(acc[1][3], a1p, b23.y);
        FMA2(acc[2][0], a2p, b01.x); FMA2(acc[2][1], a2p, b01.y);
        FMA2(acc[2][2], a2p, b23.x); FMA2(acc[2][3], a2p, b23.y);
        FMA2(acc[3][0], a3p, b01.x); FMA2(acc[3][1], a3p, b01.y);
        FMA2(acc[3][2], a3p, b23.x); FMA2(acc[3][3], a3p, b23.y);
    }

#pragma unroll
    for (int i = 0; i < 4; i++) {
        int row = row0 + rg * 4 + i;
        if (row < N_NODES) {
            float df = s_dflag[rg * 4 + i];
            float o[8];
#pragma unroll
            for (int j = 0; j < 4; j++) {
                unsigned lo, hi;
                asm("mov.b64 {%0, %1}, %2;" : "=r"(lo), "=r"(hi)
                    : "l"(acc[i][j]));
                o[2 * j + 0] = __uint_as_float(lo) + df * s_bias[cg * 8 + 2 * j + 0];
                o[2 * j + 1] = __uint_as_float(hi) + df * s_bias[cg * 8 + 2 * j + 1];
            }
            float4* dst = (float4*)(out + (long long)row * 128 + cg * 8);
            dst[0] = make_float4(o[0], o[1], o[2], o[3]);
            dst[1] = make_float4(o[4], o[5], o[6], o[7]);
        }
    }
}

// ---------------------------------------------------------------------------
// Launch
// ---------------------------------------------------------------------------
extern "C" void kernel_launch(void* const* d_in, const int* in_sizes, int n_in,
                              void* d_out, int out_size) {
    const float* x   = (const float*)d_in[0];
    const int*   ei  = (const int*)d_in[1];      // int32 edge_index [2, E]
    const float* W_l = (const float*)d_in[2];
    const float* b_l = (const float*)d_in[3];
    const float* W_r = (const float*)d_in[4];
    float*       out = (float*)d_out;
    int E = in_sizes[1] / 2;
    if (E > MAXE) E = MAXE;

    const int SMEM_BYTES = (256 * 128 + TR * LDR) * (int)sizeof(float);
    cudaFuncSetAttribute(transform_kernel,
                         cudaFuncAttributeMaxDynamicSharedMemorySize,
                         SMEM_BYTES);

    zero_kernel<<<256, 256>>>();
    hist_kernel<<<2048, 256>>>(ei, E);
    scan_kernel<<<1, SCAN_T>>>();
    fill_kernel<<<2048, 256>>>(ei, E);
    aggregate_kernel<<<(N_NODES * 32 + 255) / 256, 256>>>(x);
    transform_kernel<<<(N_NODES + TR - 1) / TR, 256, SMEM_BYTES>>>(
        x, W_l, b_l, W_r, out);
}

// round 7
// speedup vs baseline: 2.3267x; 2.3267x over previous
#include <cuda_runtime.h>
#include <cuda_bf16.h>
#include <cstdint>

#define N_NODES 100000
#define F 128
#define MAXE 1600000
#define SCAN_BS 1024
#define SCAN_NB ((N_NODES + SCAN_BS - 1) / SCAN_BS)   // 98

#define TILE_M 64
#define NT2 ((N_NODES + TILE_M - 1) / TILE_M)          // 1563
#define LDAB 528                                        // bytes/row = 264 bf16 (264/2=132, 132%32=4 -> conflict-free frags)
#define OFF_AHI 0
#define OFF_ALO (TILE_M * LDAB)                         // 33792
#define OFF_BHI (2 * TILE_M * LDAB)                     // 67584
#define OFF_BLO (OFF_BHI + 128 * LDAB)                  // 135168
#define SMEM_T  (OFF_BLO + 128 * LDAB)                  // 202752

// Scratch (allocation-free rule: __device__ globals)
__device__ int   g_cnt[N_NODES];
__device__ int   g_cur[N_NODES];
__device__ int   g_off[N_NODES];
__device__ int   g_bsum[SCAN_NB + 1];
__device__ int   g_csr[MAXE];
// bf16 hi/lo packed data: one uint2 = 4 bf16 (8B); 128 feats = 32 uint2/row
__device__ uint2 g_agghi[N_NODES * 32];
__device__ uint2 g_agglo[N_NODES * 32];
__device__ uint2 g_xhi[N_NODES * 32];
__device__ uint2 g_xlo[N_NODES * 32];
__device__ uint2 g_Whi[128 * 64];   // [n][k] n-major, 256 k = 64 uint2/row
__device__ uint2 g_Wlo[128 * 64];

// ---- bf16 split helpers: hi = truncate (exact via bit ops), lo = rn(v-hi) ----
__device__ __forceinline__ uint32_t prmt_hi2(float v0, float v1) {
    // bf16x2 {lo16: hi-bits(v0), hi16: hi-bits(v1)}
    uint32_t d;
    asm("prmt.b32 %0, %1, %2, 0x7632;"
        : "=r"(d) : "r"(__float_as_uint(v0)), "r"(__float_as_uint(v1)));
    return d;
}
__device__ __forceinline__ float trunc_hi(float v) {
    return __uint_as_float(__float_as_uint(v) & 0xFFFF0000u);
}
__device__ __forceinline__ uint32_t cvt2(float f0, float f1) {
    // bf16x2 with low half = rn(f0), high half = rn(f1)
    uint32_t d;
    asm("cvt.rn.bf16x2.f32 %0, %1, %2;" : "=r"(d) : "f"(f1), "f"(f0));
    return d;
}
__device__ __forceinline__ void split4(float4 v, uint2& hi, uint2& lo) {
    hi.x = prmt_hi2(v.x, v.y);
    hi.y = prmt_hi2(v.z, v.w);
    lo.x = cvt2(v.x - trunc_hi(v.x), v.y - trunc_hi(v.y));
    lo.y = cvt2(v.z - trunc_hi(v.z), v.w - trunc_hi(v.w));
}

#define MMA16816(c, a0, a1, a2, a3, b0, b1) \
    asm volatile("mma.sync.aligned.m16n8k16.row.col.f32.bf16.bf16.f32 " \
                 "{%0,%1,%2,%3}, {%4,%5,%6,%7}, {%8,%9}, {%0,%1,%2,%3};" \
                 : "+f"((c)[0]), "+f"((c)[1]), "+f"((c)[2]), "+f"((c)[3]) \
                 : "r"(a0), "r"(a1), "r"(a2), "r"(a3), "r"(b0), "r"(b1))

// ======================== graph preprocessing ==============================
__global__ void zero_kernel() {
    int idx = blockIdx.x * blockDim.x + threadIdx.x;
    int stride = gridDim.x * blockDim.x;
    for (int i = idx; i < N_NODES; i += stride) { g_cnt[i] = 0; g_cur[i] = 0; }
}

__global__ void hist_kernel(const int* __restrict__ ei, int E) {
    int idx = blockIdx.x * blockDim.x + threadIdx.x;
    int stride = gridDim.x * blockDim.x;
    for (int e = idx; e < E; e += stride) {
        int d = ei[E + e];
        if ((unsigned)d < (unsigned)N_NODES) atomicAdd(&g_cnt[d], 1);
    }
}

__global__ void scan1_kernel() {
    __shared__ int s[SCAN_BS];
    int tid = threadIdx.x;
    int i = blockIdx.x * SCAN_BS + tid;
    int v = (i < N_NODES) ? g_cnt[i] : 0;
    s[tid] = v;
    __syncthreads();
#pragma unroll
    for (int d = 1; d < SCAN_BS; d <<= 1) {
        int t = (tid >= d) ? s[tid - d] : 0;
        __syncthreads();
        s[tid] += t;
        __syncthreads();
    }
    if (i < N_NODES) g_off[i] = s[tid] - v;
    if (tid == SCAN_BS - 1) g_bsum[blockIdx.x] = s[tid];
}

__global__ void scan2_kernel() {
    if (threadIdx.x == 0) {
        int run = 0;
        for (int b = 0; b < SCAN_NB; b++) { int t = g_bsum[b]; g_bsum[b] = run; run += t; }
    }
}

__global__ void scan3_kernel() {
    int i = blockIdx.x * SCAN_BS + threadIdx.x;
    if (i < N_NODES) g_off[i] += g_bsum[blockIdx.x];
}

__global__ void fill_kernel(const int* __restrict__ ei, int E) {
    int idx = blockIdx.x * blockDim.x + threadIdx.x;
    int stride = gridDim.x * blockDim.x;
    for (int e = idx; e < E; e += stride) {
        int s = ei[e];
        int d = ei[E + e];
        if ((unsigned)s >= (unsigned)N_NODES ||
            (unsigned)d >= (unsigned)N_NODES) continue;
        int p = atomicAdd(&g_cur[d], 1);
        g_csr[g_off[d] + p] = s;
    }
}

// ---- aggregate: warp per node; mean of neighbors; emit bf16 hi/lo split ----
__global__ void aggregate_kernel(const float* __restrict__ x) {
    int gtid = blockIdx.x * blockDim.x + threadIdx.x;
    int w = gtid >> 5;
    int lane = gtid & 31;
    if (w >= N_NODES) return;
    int off = g_off[w];
    int deg = g_cnt[w];
    int end = off + deg;

    float4 accA = make_float4(0.f, 0.f, 0.f, 0.f);
    float4 accB = make_float4(0.f, 0.f, 0.f, 0.f);
    int i = off;
    for (; i + 8 <= end; i += 8) {
        int s0 = g_csr[i+0], s1 = g_csr[i+1], s2 = g_csr[i+2], s3 = g_csr[i+3];
        int s4 = g_csr[i+4], s5 = g_csr[i+5], s6 = g_csr[i+6], s7 = g_csr[i+7];
        float4 v0 = ((const float4*)(x + (long long)s0 * F))[lane];
        float4 v1 = ((const float4*)(x + (long long)s1 * F))[lane];
        float4 v2 = ((const float4*)(x + (long long)s2 * F))[lane];
        float4 v3 = ((const float4*)(x + (long long)s3 * F))[lane];
        float4 v4 = ((const float4*)(x + (long long)s4 * F))[lane];
        float4 v5 = ((const float4*)(x + (long long)s5 * F))[lane];
        float4 v6 = ((const float4*)(x + (long long)s6 * F))[lane];
        float4 v7 = ((const float4*)(x + (long long)s7 * F))[lane];
        accA.x += (v0.x+v1.x)+(v2.x+v3.x); accA.y += (v0.y+v1.y)+(v2.y+v3.y);
        accA.z += (v0.z+v1.z)+(v2.z+v3.z); accA.w += (v0.w+v1.w)+(v2.w+v3.w);
        accB.x += (v4.x+v5.x)+(v6.x+v7.x); accB.y += (v4.y+v5.y)+(v6.y+v7.y);
        accB.z += (v4.z+v5.z)+(v6.z+v7.z); accB.w += (v4.w+v5.w)+(v6.w+v7.w);
    }
    for (; i < end; i++) {
        int s = g_csr[i];
        float4 v = ((const float4*)(x + (long long)s * F))[lane];
        accA.x += v.x; accA.y += v.y; accA.z += v.z; accA.w += v.w;
    }
    float sc = 1.f / fmaxf((float)deg, 1.f);
    float4 o;
    o.x = (accA.x+accB.x)*sc; o.y = (accA.y+accB.y)*sc;
    o.z = (accA.z+accB.z)*sc; o.w = (accA.w+accB.w)*sc;
    uint2 hi, lo;
    split4(o, hi, lo);
    g_agghi[w * 32 + lane] = hi;
    g_agglo[w * 32 + lane] = lo;
}

// ---- x-convert: one pass, fp32 -> bf16 hi/lo ----
__global__ void xconv_kernel(const float* __restrict__ x) {
    int idx = blockIdx.x * blockDim.x + threadIdx.x;
    int stride = gridDim.x * blockDim.x;
    for (int i = idx; i < N_NODES * 32; i += stride) {
        float4 v = ((const float4*)x)[i];
        uint2 hi, lo;
        split4(v, hi, lo);
        g_xhi[i] = hi;
        g_xlo[i] = lo;
    }
}

// ---- W-convert: W256[n][k] = [W_l | W_r] -> bf16 hi/lo ----
__global__ void wconv_kernel(const float* __restrict__ W_l,
                             const float* __restrict__ W_r) {
    int idx = blockIdx.x * blockDim.x + threadIdx.x;   // [0, 128*64)
    if (idx >= 128 * 64) return;
    int n = idx >> 6;
    int kq = idx & 63;
    int k = kq * 4;
    const float* src = (k < 128) ? (W_l + n * 128 + k) : (W_r + n * 128 + (k - 128));
    float4 v = *(const float4*)src;
    uint2 hi, lo;
    split4(v, hi, lo);
    g_Whi[idx] = hi;
    g_Wlo[idx] = lo;
}

// ===================== HMMA bf16x3 transform ===============================
// out[m][n] = sum_k in256[m][k]*W256[n][k] + 1{deg>0}*b_l[n]
// in256 = [agg | x]; split products: Ahi*Bhi + Ahi*Blo + Alo*Bhi.
// Persistent: 148 CTAs x 256 thr (8 warps). Tile 64 rows x 128 cols.
// Warp (wid&3) -> row band of 16; (wid>>2) -> col half of 64 (8 n8-tiles).
__global__ void __launch_bounds__(256, 1)
transform_hmma(const float* __restrict__ b_l, float* __restrict__ out) {
    extern __shared__ char sm[];
    __shared__ float s_bias[128];
    __shared__ float s_dflag[TILE_M];

    int tid = threadIdx.x;
    int wid = tid >> 5;
    int lane = tid & 31;
    if (tid < 128) s_bias[tid] = b_l[tid];

    // B fill once: g_Whi/g_Wlo -> padded smem rows
    for (int idx = tid; idx < 128 * 64; idx += 256) {
        int n = idx >> 6;
        int kq = idx & 63;
        *(uint2*)(sm + OFF_BHI + n * LDAB + kq * 8) = g_Whi[idx];
        *(uint2*)(sm + OFF_BLO + n * LDAB + kq * 8) = g_Wlo[idx];
    }

    int wr = (wid & 3) * 16;   // warp row band
    int nb = (wid >> 2) * 64;  // warp col base
    int g = lane >> 2;
    int tg = lane & 3;

    for (int tile = blockIdx.x; tile < NT2; tile += gridDim.x) {
        int row0 = tile * TILE_M;
        __syncthreads();   // prior k-loop reads done (and B fill on iter 0)

        // A fill: 64 rows x 64 quads (hi & lo)
        for (int idx = tid; idx < TILE_M * 64; idx += 256) {
            int r = idx >> 6;
            int kq = idx & 63;
            int row = row0 + r;
            uint2 vh = make_uint2(0u, 0u), vl = make_uint2(0u, 0u);
            if (row < N_NODES) {
                int gi = (kq < 32) ? (row * 32 + kq) : (row * 32 + kq - 32);
                if (kq < 32) { vh = g_agghi[gi]; vl = g_agglo[gi]; }
                else         { vh = g_xhi[gi];   vl = g_xlo[gi];   }
            }
            *(uint2*)(sm + OFF_AHI + r * LDAB + kq * 8) = vh;
            *(uint2*)(sm + OFF_ALO + r * LDAB + kq * 8) = vl;
        }
        if (tid < TILE_M) {
            int row = row0 + tid;
            s_dflag[tid] = (row < N_NODES && g_cnt[row] > 0) ? 1.f : 0.f;
        }
        __syncthreads();

        float acc[8][4];
#pragma unroll
        for (int nt = 0; nt < 8; nt++)
#pragma unroll
            for (int j = 0; j < 4; j++) acc[nt][j] = 0.f;

        const char* aHiBase = sm + OFF_AHI + (wr + g) * LDAB + tg * 4;
        const char* aLoBase = sm + OFF_ALO + (wr + g) * LDAB + tg * 4;

#pragma unroll 4
        for (int ks = 0; ks < 16; ks++) {
            int kb = ks * 32;   // byte offset of this k16 chunk
            uint32_t a0 = *(const uint32_t*)(aHiBase + kb);
            uint32_t a1 = *(const uint32_t*)(aHiBase + kb + 8 * LDAB);
            uint32_t a2 = *(const uint32_t*)(aHiBase + kb + 16);
            uint32_t a3 = *(const uint32_t*)(aHiBase + kb + 8 * LDAB + 16);
            uint32_t l0 = *(const uint32_t*)(aLoBase + kb);
            uint32_t l1 = *(const uint32_t*)(aLoBase + kb + 8 * LDAB);
            uint32_t l2 = *(const uint32_t*)(aLoBase + kb + 16);
            uint32_t l3 = *(const uint32_t*)(aLoBase + kb + 8 * LDAB + 16);
#pragma unroll
            for (int nt = 0; nt < 8; nt++) {
                int nrow = nb + nt * 8 + g;
                const char* bh = sm + OFF_BHI + nrow * LDAB + tg * 4 + kb;
                const char* bl = sm + OFF_BLO + nrow * LDAB + tg * 4 + kb;
                uint32_t bh0 = *(const uint32_t*)bh;
                uint32_t bh1 = *(const uint32_t*)(bh + 16);
                uint32_t bl0 = *(const uint32_t*)bl;
                uint32_t bl1 = *(const uint32_t*)(bl + 16);
                MMA16816(acc[nt], a0, a1, a2, a3, bh0, bh1);
                MMA16816(acc[nt], a0, a1, a2, a3, bl0, bl1);
                MMA16816(acc[nt], l0, l1, l2, l3, bh0, bh1);
            }
        }

        // Epilogue: bias + store (float2 per reg-pair)
        int r0 = row0 + wr + g;
        int r1 = r0 + 8;
        float df0 = s_dflag[wr + g];
        float df1 = s_dflag[wr + g + 8];
#pragma unroll
        for (int nt = 0; nt < 8; nt++) {
            int col = nb + nt * 8 + tg * 2;
            float b0 = s_bias[col], b1 = s_bias[col + 1];
            if (r0 < N_NODES) {
                float2 v = make_float2(acc[nt][0] + df0 * b0,
                                       acc[nt][1] + df0 * b1);
                *(float2*)(out + (long long)r0 * 128 + col) = v;
            }
            if (r1 < N_NODES) {
                float2 v = make_float2(acc[nt][2] + df1 * b0,
                                       acc[nt][3] + df1 * b1);
                *(float2*)(out + (long long)r1 * 128 + col) = v;
            }
        }
    }
}

// ---------------------------------------------------------------------------
// Launch
// ---------------------------------------------------------------------------
extern "C" void kernel_launch(void* const* d_in, const int* in_sizes, int n_in,
                              void* d_out, int out_size) {
    const float* x   = (const float*)d_in[0];
    const int*   ei  = (const int*)d_in[1];
    const float* W_l = (const float*)d_in[2];
    const float* b_l = (const float*)d_in[3];
    const float* W_r = (const float*)d_in[4];
    float*       out = (float*)d_out;
    int E = in_sizes[1] / 2;
    if (E > MAXE) E = MAXE;

    cudaFuncSetAttribute(transform_hmma,
                         cudaFuncAttributeMaxDynamicSharedMemorySize, SMEM_T);

    zero_kernel<<<256, 256>>>();
    hist_kernel<<<2048, 256>>>(ei, E);
    scan1_kernel<<<SCAN_NB, SCAN_BS>>>();
    scan2_kernel<<<1, 32>>>();
    scan3_kernel<<<SCAN_NB, SCAN_BS>>>();
    fill_kernel<<<2048, 256>>>(ei, E);
    xconv_kernel<<<2048, 256>>>(x);
    wconv_kernel<<<32, 256>>>(W_l, W_r);
    aggregate_kernel<<<(N_NODES * 32 + 255) / 256, 256>>>(x);
    transform_hmma<<<148, 256, SMEM_T>>>(b_l, out);
}

// round 8
// speedup vs baseline: 3.1167x; 1.3395x over previous
#include <cuda_runtime.h>
#include <cuda_bf16.h>
#include <cstdint>

#define N_NODES 100000
#define F 128
#define MAXE 1600000
#define SCAN_BS 1024
#define SCAN_NB ((N_NODES + SCAN_BS - 1) / SCAN_BS)   // 98

#define TILE_M 64
#define NT2 ((N_NODES + TILE_M - 1) / TILE_M)          // 1563
#define LDAB 528                                        // bytes/row = 264 bf16; 33 16B-units -> conflict-free ldmatrix
#define OFF_AHI 0
#define OFF_ALO (TILE_M * LDAB)                         // 33792
#define OFF_BHI (2 * TILE_M * LDAB)                     // 67584
#define OFF_BLO (OFF_BHI + 128 * LDAB)                  // 135168
#define SMEM_T  (OFF_BLO + 128 * LDAB)                  // 202752

// Scratch (allocation-free rule: __device__ globals)
__device__ int   g_cnt[N_NODES];
__device__ int   g_cur[N_NODES];
__device__ int   g_off[N_NODES];
__device__ int   g_bsum[SCAN_NB + 1];
__device__ int   g_csr[MAXE];
// bf16 hi/lo packed data: one uint2 = 4 bf16 (8B); 128 feats = 32 uint2/row
__device__ uint2 g_agghi[N_NODES * 32];
__device__ uint2 g_agglo[N_NODES * 32];
__device__ uint2 g_xhi[N_NODES * 32];
__device__ uint2 g_xlo[N_NODES * 32];

// ---- bf16 split helpers: hi = truncate (exact via bit ops), lo = rn(v-hi) ----
__device__ __forceinline__ uint32_t prmt_hi2(float v0, float v1) {
    uint32_t d;
    asm("prmt.b32 %0, %1, %2, 0x7632;"
        : "=r"(d) : "r"(__float_as_uint(v0)), "r"(__float_as_uint(v1)));
    return d;
}
__device__ __forceinline__ float trunc_hi(float v) {
    return __uint_as_float(__float_as_uint(v) & 0xFFFF0000u);
}
__device__ __forceinline__ uint32_t cvt2(float f0, float f1) {
    uint32_t d;
    asm("cvt.rn.bf16x2.f32 %0, %1, %2;" : "=r"(d) : "f"(f1), "f"(f0));
    return d;
}
__device__ __forceinline__ void split4(float4 v, uint2& hi, uint2& lo) {
    hi.x = prmt_hi2(v.x, v.y);
    hi.y = prmt_hi2(v.z, v.w);
    lo.x = cvt2(v.x - trunc_hi(v.x), v.y - trunc_hi(v.y));
    lo.y = cvt2(v.z - trunc_hi(v.z), v.w - trunc_hi(v.w));
}

#define MMA16816(c, a0, a1, a2, a3, b0, b1) \
    asm volatile("mma.sync.aligned.m16n8k16.row.col.f32.bf16.bf16.f32 " \
                 "{%0,%1,%2,%3}, {%4,%5,%6,%7}, {%8,%9}, {%0,%1,%2,%3};" \
                 : "+f"((c)[0]), "+f"((c)[1]), "+f"((c)[2]), "+f"((c)[3]) \
                 : "r"(a0), "r"(a1), "r"(a2), "r"(a3), "r"(b0), "r"(b1))
#define LDSM4(r0, r1, r2, r3, addr) \
    asm volatile("ldmatrix.sync.aligned.m8n8.x4.shared.b16 {%0,%1,%2,%3}, [%4];" \
                 : "=r"(r0), "=r"(r1), "=r"(r2), "=r"(r3) : "r"(addr))
#define LDSM2(r0, r1, addr) \
    asm volatile("ldmatrix.sync.aligned.m8n8.x2.shared.b16 {%0,%1}, [%2];" \
                 : "=r"(r0), "=r"(r1) : "r"(addr))

__device__ __forceinline__ uint32_t smem_u32(const void* p) {
    uint32_t a;
    asm("{ .reg .u64 t; cvta.to.shared.u64 t, %1; cvt.u32.u64 %0, t; }"
        : "=r"(a) : "l"(p));
    return a;
}

// ======================== graph preprocessing ==============================
__global__ void zero_kernel() {
    int idx = blockIdx.x * blockDim.x + threadIdx.x;
    int stride = gridDim.x * blockDim.x;
    for (int i = idx; i < N_NODES; i += stride) g_cnt[i] = 0;
}

__global__ void hist_kernel(const int* __restrict__ ei, int E) {
    int idx = blockIdx.x * blockDim.x + threadIdx.x;
    int stride = gridDim.x * blockDim.x;
    for (int e = idx; e < E; e += stride) {
        int d = ei[E + e];
        if ((unsigned)d < (unsigned)N_NODES) atomicAdd(&g_cnt[d], 1);
    }
}

__global__ void scan1_kernel() {
    __shared__ int s[SCAN_BS];
    int tid = threadIdx.x;
    int i = blockIdx.x * SCAN_BS + tid;
    int v = (i < N_NODES) ? g_cnt[i] : 0;
    s[tid] = v;
    __syncthreads();
#pragma unroll
    for (int d = 1; d < SCAN_BS; d <<= 1) {
        int t = (tid >= d) ? s[tid - d] : 0;
        __syncthreads();
        s[tid] += t;
        __syncthreads();
    }
    if (i < N_NODES) g_off[i] = s[tid] - v;
    if (tid == SCAN_BS - 1) g_bsum[blockIdx.x] = s[tid];
}

__global__ void scan2_kernel() {   // parallel 128-thread Kogge-Stone over 98 sums
    __shared__ int s[128];
    int tid = threadIdx.x;
    int v = (tid < SCAN_NB) ? g_bsum[tid] : 0;
    s[tid] = v;
    __syncthreads();
#pragma unroll
    for (int d = 1; d < 128; d <<= 1) {
        int t = (tid >= d) ? s[tid - d] : 0;
        __syncthreads();
        s[tid] += t;
        __syncthreads();
    }
    if (tid < SCAN_NB) g_bsum[tid] = s[tid] - v;   // exclusive
}

__global__ void scan3_kernel() {
    int i = blockIdx.x * SCAN_BS + threadIdx.x;
    if (i < N_NODES) {
        g_off[i] += g_bsum[blockIdx.x];
        g_cur[i] = 0;
    }
}

__global__ void fill_kernel(const int* __restrict__ ei, int E) {
    int idx = blockIdx.x * blockDim.x + threadIdx.x;
    int stride = gridDim.x * blockDim.x;
    for (int e = idx; e < E; e += stride) {
        int s = ei[e];
        int d = ei[E + e];
        if ((unsigned)s >= (unsigned)N_NODES ||
            (unsigned)d >= (unsigned)N_NODES) continue;
        int p = atomicAdd(&g_cur[d], 1);
        g_csr[g_off[d] + p] = s;
    }
}

// ---- aggregate: warp per node; mean of neighbors; emit bf16 hi/lo split ----
__global__ void aggregate_kernel(const float* __restrict__ x) {
    int gtid = blockIdx.x * blockDim.x + threadIdx.x;
    int w = gtid >> 5;
    int lane = gtid & 31;
    if (w >= N_NODES) return;
    int off = g_off[w];
    int deg = g_cnt[w];
    int end = off + deg;

    float4 accA = make_float4(0.f, 0.f, 0.f, 0.f);
    float4 accB = make_float4(0.f, 0.f, 0.f, 0.f);
    int i = off;
    for (; i + 8 <= end; i += 8) {
        int s0 = g_csr[i+0], s1 = g_csr[i+1], s2 = g_csr[i+2], s3 = g_csr[i+3];
        int s4 = g_csr[i+4], s5 = g_csr[i+5], s6 = g_csr[i+6], s7 = g_csr[i+7];
        float4 v0 = ((const float4*)(x + (long long)s0 * F))[lane];
        float4 v1 = ((const float4*)(x + (long long)s1 * F))[lane];
        float4 v2 = ((const float4*)(x + (long long)s2 * F))[lane];
        float4 v3 = ((const float4*)(x + (long long)s3 * F))[lane];
        float4 v4 = ((const float4*)(x + (long long)s4 * F))[lane];
        float4 v5 = ((const float4*)(x + (long long)s5 * F))[lane];
        float4 v6 = ((const float4*)(x + (long long)s6 * F))[lane];
        float4 v7 = ((const float4*)(x + (long long)s7 * F))[lane];
        accA.x += (v0.x+v1.x)+(v2.x+v3.x); accA.y += (v0.y+v1.y)+(v2.y+v3.y);
        accA.z += (v0.z+v1.z)+(v2.z+v3.z); accA.w += (v0.w+v1.w)+(v2.w+v3.w);
        accB.x += (v4.x+v5.x)+(v6.x+v7.x); accB.y += (v4.y+v5.y)+(v6.y+v7.y);
        accB.z += (v4.z+v5.z)+(v6.z+v7.z); accB.w += (v4.w+v5.w)+(v6.w+v7.w);
    }
    for (; i < end; i++) {
        int s = g_csr[i];
        float4 v = ((const float4*)(x + (long long)s * F))[lane];
        accA.x += v.x; accA.y += v.y; accA.z += v.z; accA.w += v.w;
    }
    float sc = 1.f / fmaxf((float)deg, 1.f);
    float4 o;
    o.x = (accA.x+accB.x)*sc; o.y = (accA.y+accB.y)*sc;
    o.z = (accA.z+accB.z)*sc; o.w = (accA.w+accB.w)*sc;
    uint2 hi, lo;
    split4(o, hi, lo);
    g_agghi[w * 32 + lane] = hi;
    g_agglo[w * 32 + lane] = lo;
}

// ---- x-convert: one pass, fp32 -> bf16 hi/lo ----
__global__ void xconv_kernel(const float* __restrict__ x) {
    int idx = blockIdx.x * blockDim.x + threadIdx.x;
    int stride = gridDim.x * blockDim.x;
    for (int i = idx; i < N_NODES * 32; i += stride) {
        float4 v = ((const float4*)x)[i];
        uint2 hi, lo;
        split4(v, hi, lo);
        g_xhi[i] = hi;
        g_xlo[i] = lo;
    }
}

// ===================== HMMA bf16x3 transform (ldmatrix) ====================
// out[m][n] = sum_k in256[m][k]*W256[n][k] + 1{deg>0}*b_l[n]
// in256 = [agg | x]; split products: Ahi*Bhi + Ahi*Blo + Alo*Bhi.
// Persistent: 148 CTAs x 256 thr (8 warps). Tile 64 rows x 128 cols.
__global__ void __launch_bounds__(256, 1)
transform_hmma(const float* __restrict__ W_l,
               const float* __restrict__ b_l,
               const float* __restrict__ W_r,
               float* __restrict__ out) {
    extern __shared__ char sm[];
    __shared__ float s_bias[128];
    __shared__ float s_dflag[TILE_M];

    int tid = threadIdx.x;
    int wid = tid >> 5;
    int lane = tid & 31;
    uint32_t sbase = smem_u32(sm);
    if (tid < 128) s_bias[tid] = b_l[tid];

    // B fill once: W -> bf16 hi/lo into padded smem rows
    for (int idx = tid; idx < 128 * 64; idx += 256) {
        int n = idx >> 6;
        int kq = idx & 63;
        int k = kq * 4;
        const float* src = (k < 128) ? (W_l + n * 128 + k)
                                     : (W_r + n * 128 + (k - 128));
        float4 v = *(const float4*)src;
        uint2 hi, lo;
        split4(v, hi, lo);
        *(uint2*)(sm + OFF_BHI + n * LDAB + kq * 8) = hi;
        *(uint2*)(sm + OFF_BLO + n * LDAB + kq * 8) = lo;
    }

    int wr = (wid & 3) * 16;   // warp row band
    int nb = (wid >> 2) * 64;  // warp col base

    // ldmatrix lane addresses
    uint32_t aHi = sbase + OFF_AHI + (wr + (lane & 15)) * LDAB + ((lane >> 4) & 1) * 16;
    uint32_t aLo = aHi + (OFF_ALO - OFF_AHI);
    uint32_t bHi = sbase + OFF_BHI + (nb + (lane & 7)) * LDAB + ((lane >> 3) & 1) * 16;
    uint32_t bLo = bHi + (OFF_BLO - OFF_BHI);

    for (int tile = blockIdx.x; tile < NT2; tile += gridDim.x) {
        int row0 = tile * TILE_M;
        __syncthreads();   // prior k-loop reads done (and B fill on iter 0)

        // A fill: uint4 granularity. 64 rows x 16 uint4 per array.
        for (int idx = tid; idx < TILE_M * 16; idx += 256) {
            int r = idx >> 4;
            int u = idx & 15;
            int row = row0 + r;
            uint4 vah = make_uint4(0,0,0,0), val = vah, vxh = vah, vxl = vah;
            if (row < N_NODES) {
                long long base = (long long)row * 32;
                vah = ((const uint4*)(const void*)(g_agghi + base))[u];
                val = ((const uint4*)(const void*)(g_agglo + base))[u];
                vxh = ((const uint4*)(const void*)(g_xhi + base))[u];
                vxl = ((const uint4*)(const void*)(g_xlo + base))[u];
            }
            char* rowp = sm + r * LDAB + u * 16;
            *(uint4*)(rowp + OFF_AHI) = vah;
            *(uint4*)(rowp + OFF_AHI + 256) = vxh;
            *(uint4*)(rowp + OFF_ALO) = val;
            *(uint4*)(rowp + OFF_ALO + 256) = vxl;
        }
        if (tid < TILE_M) {
            int row = row0 + tid;
            s_dflag[tid] = (row < N_NODES && g_cnt[row] > 0) ? 1.f : 0.f;
        }
        __syncthreads();

        float acc[8][4];
#pragma unroll
        for (int nt = 0; nt < 8; nt++)
#pragma unroll
            for (int j = 0; j < 4; j++) acc[nt][j] = 0.f;

#pragma unroll 2
        for (int ks = 0; ks < 16; ks++) {
            int kb = ks * 32;
            uint32_t a0, a1, a2, a3, l0, l1, l2, l3;
            LDSM4(a0, a1, a2, a3, aHi + kb);
            LDSM4(l0, l1, l2, l3, aLo + kb);
#pragma unroll
            for (int nt = 0; nt < 8; nt++) {
                uint32_t bh0, bh1, bl0, bl1;
                LDSM2(bh0, bh1, bHi + nt * 8 * LDAB + kb);
                LDSM2(bl0, bl1, bLo + nt * 8 * LDAB + kb);
                MMA16816(acc[nt], a0, a1, a2, a3, bh0, bh1);
                MMA16816(acc[nt], a0, a1, a2, a3, bl0, bl1);
                MMA16816(acc[nt], l0, l1, l2, l3, bh0, bh1);
            }
        }

        // Epilogue: bias + store (float2 per reg-pair)
        int g = lane >> 2;
        int tg = lane & 3;
        int r0 = row0 + wr + g;
        int r1 = r0 + 8;
        float df0 = s_dflag[wr + g];
        float df1 = s_dflag[wr + g + 8];
#pragma unroll
        for (int nt = 0; nt < 8; nt++) {
            int col = nb + nt * 8 + tg * 2;
            float b0 = s_bias[col], b1 = s_bias[col + 1];
            if (r0 < N_NODES) {
                float2 v = make_float2(acc[nt][0] + df0 * b0,
                                       acc[nt][1] + df0 * b1);
                *(float2*)(out + (long long)r0 * 128 + col) = v;
            }
            if (r1 < N_NODES) {
                float2 v = make_float2(acc[nt][2] + df1 * b0,
                                       acc[nt][3] + df1 * b1);
                *(float2*)(out + (long long)r1 * 128 + col) = v;
            }
        }
    }
}

// ---------------------------------------------------------------------------
// Launch
// ---------------------------------------------------------------------------
extern "C" void kernel_launch(void* const* d_in, const int* in_sizes, int n_in,
                              void* d_out, int out_size) {
    const float* x   = (const float*)d_in[0];
    const int*   ei  = (const int*)d_in[1];
    const float* W_l = (const float*)d_in[2];
    const float* b_l = (const float*)d_in[3];
    const float* W_r = (const float*)d_in[4];
    float*       out = (float*)d_out;
    int E = in_sizes[1] / 2;
    if (E > MAXE) E = MAXE;

    cudaFuncSetAttribute(transform_hmma,
                         cudaFuncAttributeMaxDynamicSharedMemorySize, SMEM_T);

    zero_kernel<<<256, 256>>>();
    hist_kernel<<<2048, 256>>>(ei, E);
    scan1_kernel<<<SCAN_NB, SCAN_BS>>>();
    scan2_kernel<<<1, 128>>>();
    scan3_kernel<<<SCAN_NB, SCAN_BS>>>();
    fill_kernel<<<2048, 256>>>(ei, E);
    xconv_kernel<<<2048, 256>>>(x);
    aggregate_kernel<<<(N_NODES * 32 + 255) / 256, 256>>>(x);
    transform_hmma<<<148, 256, SMEM_T>>>(W_l, b_l, W_r, out);
}

// round 9
// speedup vs baseline: 3.6963x; 1.1860x over previous
#include <cuda_runtime.h>
#include <cuda_bf16.h>
#include <cstdint>

#define N_NODES 100000
#define F 128
#define MAXE 1600000
#define SCAN_BS 1024
#define SCAN_NB ((N_NODES + SCAN_BS - 1) / SCAN_BS)   // 98

#define TILE_M 32
#define NT2 (N_NODES / TILE_M)                         // 3125 exact
#define LDAB 528                                       // 512B data + 16B pad; 33x16B units
#define ABUF_LO 16896                                  // lo half offset inside an A buffer
#define ABUF_SZ 33792                                  // one A buffer (hi+lo)
#define OFF_BHI (2 * ABUF_SZ)                          // 67584
#define OFF_BLO (OFF_BHI + 128 * LDAB)                 // 135168
#define SMEM_T  (OFF_BLO + 128 * LDAB)                 // 202752

// Scratch (allocation-free rule: __device__ globals)
__device__ int   g_cnt[N_NODES];
__device__ int   g_cur[N_NODES];
__device__ int   g_off[N_NODES];
__device__ int   g_bsum[SCAN_NB + 1];
__device__ int   g_csr[MAXE];
// bf16 hi/lo packed: one uint2 = 4 bf16 (8B); 128 feats = 32 uint2 = 256B/row
__device__ uint2 g_agghi[N_NODES * 32];
__device__ uint2 g_agglo[N_NODES * 32];
__device__ uint2 g_xhi[N_NODES * 32];
__device__ uint2 g_xlo[N_NODES * 32];

// ---- bf16 split helpers: hi = truncate (exact bits), lo = rn(v-hi) ----
__device__ __forceinline__ uint32_t prmt_hi2(float v0, float v1) {
    uint32_t d;
    asm("prmt.b32 %0, %1, %2, 0x7632;"
        : "=r"(d) : "r"(__float_as_uint(v0)), "r"(__float_as_uint(v1)));
    return d;
}
__device__ __forceinline__ float trunc_hi(float v) {
    return __uint_as_float(__float_as_uint(v) & 0xFFFF0000u);
}
__device__ __forceinline__ uint32_t cvt2(float f0, float f1) {
    uint32_t d;
    asm("cvt.rn.bf16x2.f32 %0, %1, %2;" : "=r"(d) : "f"(f1), "f"(f0));
    return d;
}
__device__ __forceinline__ void split4(float4 v, uint2& hi, uint2& lo) {
    hi.x = prmt_hi2(v.x, v.y);
    hi.y = prmt_hi2(v.z, v.w);
    lo.x = cvt2(v.x - trunc_hi(v.x), v.y - trunc_hi(v.y));
    lo.y = cvt2(v.z - trunc_hi(v.z), v.w - trunc_hi(v.w));
}

#define MMA16816(c, a0, a1, a2, a3, b0, b1) \
    asm volatile("mma.sync.aligned.m16n8k16.row.col.f32.bf16.bf16.f32 " \
                 "{%0,%1,%2,%3}, {%4,%5,%6,%7}, {%8,%9}, {%0,%1,%2,%3};" \
                 : "+f"((c)[0]), "+f"((c)[1]), "+f"((c)[2]), "+f"((c)[3]) \
                 : "r"(a0), "r"(a1), "r"(a2), "r"(a3), "r"(b0), "r"(b1))
#define LDSM4(r0, r1, r2, r3, addr) \
    asm volatile("ldmatrix.sync.aligned.m8n8.x4.shared.b16 {%0,%1,%2,%3}, [%4];" \
                 : "=r"(r0), "=r"(r1), "=r"(r2), "=r"(r3) : "r"(addr))
#define LDSM2(r0, r1, addr) \
    asm volatile("ldmatrix.sync.aligned.m8n8.x2.shared.b16 {%0,%1}, [%2];" \
                 : "=r"(r0), "=r"(r1) : "r"(addr))
#define CP16(dst, src, ssz) \
    asm volatile("cp.async.cg.shared.global [%0], [%1], 16, %2;" \
                 :: "r"(dst), "l"(src), "r"(ssz) : "memory")
#define CP_COMMIT() asm volatile("cp.async.commit_group;" ::: "memory")
#define CP_WAIT1()  asm volatile("cp.async.wait_group 1;" ::: "memory")

__device__ __forceinline__ uint32_t smem_u32(const void* p) {
    uint32_t a;
    asm("{ .reg .u64 t; cvta.to.shared.u64 t, %1; cvt.u32.u64 %0, t; }"
        : "=r"(a) : "l"(p));
    return a;
}

// ======================== graph preprocessing ==============================
__global__ void zero_kernel() {
    int idx = blockIdx.x * blockDim.x + threadIdx.x;
    int stride = gridDim.x * blockDim.x;
    for (int i = idx; i < N_NODES; i += stride) g_cnt[i] = 0;
}

__global__ void hist_kernel(const int* __restrict__ ei, int E) {
    int idx = blockIdx.x * blockDim.x + threadIdx.x;
    int stride = gridDim.x * blockDim.x;
    for (int e = idx; e < E; e += stride) {
        int d = ei[E + e];
        if ((unsigned)d < (unsigned)N_NODES) atomicAdd(&g_cnt[d], 1);
    }
}

__global__ void scan1_kernel() {
    __shared__ int s[SCAN_BS];
    int tid = threadIdx.x;
    int i = blockIdx.x * SCAN_BS + tid;
    int v = (i < N_NODES) ? g_cnt[i] : 0;
    s[tid] = v;
    __syncthreads();
#pragma unroll
    for (int d = 1; d < SCAN_BS; d <<= 1) {
        int t = (tid >= d) ? s[tid - d] : 0;
        __syncthreads();
        s[tid] += t;
        __syncthreads();
    }
    if (i < N_NODES) g_off[i] = s[tid] - v;
    if (tid == SCAN_BS - 1) g_bsum[blockIdx.x] = s[tid];
}

__global__ void scan2_kernel() {
    __shared__ int s[128];
    int tid = threadIdx.x;
    int v = (tid < SCAN_NB) ? g_bsum[tid] : 0;
    s[tid] = v;
    __syncthreads();
#pragma unroll
    for (int d = 1; d < 128; d <<= 1) {
        int t = (tid >= d) ? s[tid - d] : 0;
        __syncthreads();
        s[tid] += t;
        __syncthreads();
    }
    if (tid < SCAN_NB) g_bsum[tid] = s[tid] - v;
}

__global__ void scan3_kernel() {
    int i = blockIdx.x * SCAN_BS + threadIdx.x;
    if (i < N_NODES) {
        int off = g_off[i] + g_bsum[blockIdx.x];
        g_off[i] = off;
        g_cur[i] = off;   // cursor starts at absolute offset
    }
}

__global__ void fill_kernel(const int* __restrict__ ei, int E) {
    int idx = blockIdx.x * blockDim.x + threadIdx.x;
    int stride = gridDim.x * blockDim.x;
    for (int e = idx; e < E; e += stride) {
        int s = ei[e];
        int d = ei[E + e];
        if ((unsigned)s >= (unsigned)N_NODES ||
            (unsigned)d >= (unsigned)N_NODES) continue;
        int p = atomicAdd(&g_cur[d], 1);   // absolute position
        g_csr[p] = s;
    }
}

// ---- aggregate (+ fused x-convert): warp per node ----
__global__ void aggregate_kernel(const float* __restrict__ x) {
    int gtid = blockIdx.x * blockDim.x + threadIdx.x;
    int w = gtid >> 5;
    int lane = gtid & 31;
    if (w >= N_NODES) return;
    int off = g_off[w];
    int deg = g_cnt[w];
    int end = off + deg;

    // fused xconv for this node's own row
    float4 xv = ((const float4*)(x + (long long)w * F))[lane];

    float4 accA = make_float4(0.f, 0.f, 0.f, 0.f);
    float4 accB = make_float4(0.f, 0.f, 0.f, 0.f);
    int i = off;
    for (; i + 8 <= end; i += 8) {
        int s0 = g_csr[i+0], s1 = g_csr[i+1], s2 = g_csr[i+2], s3 = g_csr[i+3];
        int s4 = g_csr[i+4], s5 = g_csr[i+5], s6 = g_csr[i+6], s7 = g_csr[i+7];
        float4 v0 = ((const float4*)(x + (long long)s0 * F))[lane];
        float4 v1 = ((const float4*)(x + (long long)s1 * F))[lane];
        float4 v2 = ((const float4*)(x + (long long)s2 * F))[lane];
        float4 v3 = ((const float4*)(x + (long long)s3 * F))[lane];
        float4 v4 = ((const float4*)(x + (long long)s4 * F))[lane];
        float4 v5 = ((const float4*)(x + (long long)s5 * F))[lane];
        float4 v6 = ((const float4*)(x + (long long)s6 * F))[lane];
        float4 v7 = ((const float4*)(x + (long long)s7 * F))[lane];
        accA.x += (v0.x+v1.x)+(v2.x+v3.x); accA.y += (v0.y+v1.y)+(v2.y+v3.y);
        accA.z += (v0.z+v1.z)+(v2.z+v3.z); accA.w += (v0.w+v1.w)+(v2.w+v3.w);
        accB.x += (v4.x+v5.x)+(v6.x+v7.x); accB.y += (v4.y+v5.y)+(v6.y+v7.y);
        accB.z += (v4.z+v5.z)+(v6.z+v7.z); accB.w += (v4.w+v5.w)+(v6.w+v7.w);
    }
    for (; i < end; i++) {
        int s = g_csr[i];
        float4 v = ((const float4*)(x + (long long)s * F))[lane];
        accA.x += v.x; accA.y += v.y; accA.z += v.z; accA.w += v.w;
    }
    float sc = 1.f / fmaxf((float)deg, 1.f);
    float4 o;
    o.x = (accA.x+accB.x)*sc; o.y = (accA.y+accB.y)*sc;
    o.z = (accA.z+accB.z)*sc; o.w = (accA.w+accB.w)*sc;
    uint2 hi, lo;
    split4(o, hi, lo);
    g_agghi[w * 32 + lane] = hi;
    g_agglo[w * 32 + lane] = lo;
    split4(xv, hi, lo);
    g_xhi[w * 32 + lane] = hi;
    g_xlo[w * 32 + lane] = lo;
}

// ===================== HMMA bf16x3 transform (pipelined) ===================
// out[m][n] = sum_k in256[m][k]*W256[n][k] + 1{deg>0}*b_l[n]
// in256 = [agg | x]; split: Ahi*Bhi + Ahi*Blo + Alo*Bhi.
// Persistent 148 CTAs x 256 thr. Tile 32 rows, double-buffered cp.async fill.
// A row layout: [agghi 256B | xhi 256B | pad16]; lo copy at +ABUF_LO.
__device__ __forceinline__ void prefetch_A(uint32_t sbase, int bufbase,
                                           int tile, int tid) {
    int row0 = tile * TILE_M;
    int op = tid & 63;
    int a2 = op >> 4;          // 0 agghi, 1 xhi, 2 agglo, 3 xlo
    int u = op & 15;
    const char* arr;
    if (a2 == 0)      arr = (const char*)g_agghi;
    else if (a2 == 1) arr = (const char*)g_xhi;
    else if (a2 == 2) arr = (const char*)g_agglo;
    else              arr = (const char*)g_xlo;
    uint32_t dbase = sbase + bufbase + (a2 & 1) * 256 + (a2 >> 1) * ABUF_LO + u * 16;
    int rbase = tid >> 6;      // 0..3
#pragma unroll
    for (int i = 0; i < 8; i++) {
        int r = rbase + i * 4;
        int row = row0 + r;
        int ok = (row < N_NODES) ? 16 : 0;
        const char* src = arr + (long long)min(row, N_NODES - 1) * 256 + u * 16;
        CP16(dbase + r * LDAB, src, ok);
    }
}

__global__ void __launch_bounds__(256, 1)
transform_hmma(const float* __restrict__ W_l,
               const float* __restrict__ b_l,
               const float* __restrict__ W_r,
               float* __restrict__ out) {
    extern __shared__ char sm[];
    __shared__ float s_bias[128];

    int tid = threadIdx.x;
    int wid = tid >> 5;
    int lane = tid & 31;
    uint32_t sbase = smem_u32(sm);
    if (tid < 128) s_bias[tid] = b_l[tid];

    // B fill once: W -> bf16 hi/lo
    for (int idx = tid; idx < 128 * 64; idx += 256) {
        int n = idx >> 6;
        int kq = idx & 63;
        int k = kq * 4;
        const float* src = (k < 128) ? (W_l + n * 128 + k)
                                     : (W_r + n * 128 + (k - 128));
        float4 v = *(const float4*)src;
        uint2 hi, lo;
        split4(v, hi, lo);
        *(uint2*)(sm + OFF_BHI + n * LDAB + kq * 8) = hi;
        *(uint2*)(sm + OFF_BLO + n * LDAB + kq * 8) = lo;
    }

    int wr = (wid & 1) * 16;   // warp row band (0 or 16)
    int nb = (wid >> 1) * 32;  // warp col base (0/32/64/96)

    uint32_t aOff = (wr + (lane & 15)) * LDAB + ((lane >> 4) & 1) * 16;
    uint32_t bHi = sbase + OFF_BHI + (nb + (lane & 7)) * LDAB + ((lane >> 3) & 1) * 16;
    uint32_t bLo = bHi + (OFF_BLO - OFF_BHI);

    int tile = blockIdx.x;
    prefetch_A(sbase, 0, tile, tid);
    CP_COMMIT();

    int it = 0;
    for (; tile < NT2; tile += gridDim.x, it++) {
        int ntile = tile + gridDim.x;
        if (ntile < NT2) prefetch_A(sbase, ((it + 1) & 1) * ABUF_SZ, ntile, tid);
        CP_COMMIT();
        CP_WAIT1();
        __syncthreads();

        int row0 = tile * TILE_M;
        int g = lane >> 2;
        int tg = lane & 3;
        int r0 = row0 + wr + g;
        int r1 = r0 + 8;
        int c0 = g_cnt[r0];          // LDG issued early, used in epilogue
        int c1 = g_cnt[r1];

        uint32_t abase = sbase + (it & 1) * ABUF_SZ;
        uint32_t aHi = abase + aOff;
        uint32_t aLo = aHi + ABUF_LO;

        float acc[4][4];
#pragma unroll
        for (int nt = 0; nt < 4; nt++)
#pragma unroll
            for (int j = 0; j < 4; j++) acc[nt][j] = 0.f;

#pragma unroll 2
        for (int ks = 0; ks < 16; ks++) {
            int kb = ks * 32;
            uint32_t a0, a1, a2, a3, l0, l1, l2, l3;
            LDSM4(a0, a1, a2, a3, aHi + kb);
            LDSM4(l0, l1, l2, l3, aLo + kb);
#pragma unroll
            for (int nt = 0; nt < 4; nt++) {
                uint32_t bh0, bh1, bl0, bl1;
                LDSM2(bh0, bh1, bHi + nt * 8 * LDAB + kb);
                LDSM2(bl0, bl1, bLo + nt * 8 * LDAB + kb);
                MMA16816(acc[nt], a0, a1, a2, a3, bh0, bh1);
                MMA16816(acc[nt], a0, a1, a2, a3, bl0, bl1);
                MMA16816(acc[nt], l0, l1, l2, l3, bh0, bh1);
            }
        }

        float df0 = (c0 > 0) ? 1.f : 0.f;
        float df1 = (c1 > 0) ? 1.f : 0.f;
#pragma unroll
        for (int nt = 0; nt < 4; nt++) {
            int col = nb + nt * 8 + tg * 2;
            float b0 = s_bias[col], b1 = s_bias[col + 1];
            float2 v0 = make_float2(acc[nt][0] + df0 * b0,
                                    acc[nt][1] + df0 * b1);
            *(float2*)(out + (long long)r0 * 128 + col) = v0;
            float2 v1 = make_float2(acc[nt][2] + df1 * b0,
                                    acc[nt][3] + df1 * b1);
            *(float2*)(out + (long long)r1 * 128 + col) = v1;
        }
        __syncthreads();
    }
}

// ---------------------------------------------------------------------------
// Launch
// ---------------------------------------------------------------------------
extern "C" void kernel_launch(void* const* d_in, const int* in_sizes, int n_in,
                              void* d_out, int out_size) {
    const float* x   = (const float*)d_in[0];
    const int*   ei  = (const int*)d_in[1];
    const float* W_l = (const float*)d_in[2];
    const float* b_l = (const float*)d_in[3];
    const float* W_r = (const float*)d_in[4];
    float*       out = (float*)d_out;
    int E = in_sizes[1] / 2;
    if (E > MAXE) E = MAXE;

    cudaFuncSetAttribute(transform_hmma,
                         cudaFuncAttributeMaxDynamicSharedMemorySize, SMEM_T);

    zero_kernel<<<256, 256>>>();
    hist_kernel<<<2048, 256>>>(ei, E);
    scan1_kernel<<<SCAN_NB, SCAN_BS>>>();
    scan2_kernel<<<1, 128>>>();
    scan3_kernel<<<SCAN_NB, SCAN_BS>>>();
    fill_kernel<<<2048, 256>>>(ei, E);
    aggregate_kernel<<<(N_NODES * 32 + 255) / 256, 256>>>(x);
    transform_hmma<<<148, 256, SMEM_T>>>(W_l, b_l, W_r, out);
}

// round 10
// speedup vs baseline: 3.9074x; 1.0571x over previous
#include <cuda_runtime.h>
#include <cuda_bf16.h>
#include <cstdint>

#define N_NODES 100000
#define F 128
#define MAXE 1600000
#define SCAN_BS 1024
#define SCAN_NB ((N_NODES + SCAN_BS - 1) / SCAN_BS)   // 98

#define TILE_M 32
#define NT2 (N_NODES / TILE_M)                         // 3125 exact
#define LDAB 528                                       // 512B data + 16B pad
#define ABUF_LO 16896
#define ABUF_SZ 33792
#define OFF_BHI (2 * ABUF_SZ)                          // 67584
#define OFF_BLO (OFF_BHI + 128 * LDAB)                 // 135168
#define SMEM_T  (OFF_BLO + 128 * LDAB)                 // 202752

// Scratch (allocation-free rule: __device__ globals)
__device__ int   g_cnt[N_NODES];
__device__ int   g_cur[N_NODES];
__device__ int   g_off[N_NODES];
__device__ int   g_bsum[SCAN_NB + 1];
__device__ int   g_csr[MAXE];
// bf16 hi/lo packed: one uint2 = 4 bf16 (8B); 128 feats = 32 uint2 = 256B/row
__device__ uint2 g_agghi[N_NODES * 32];
__device__ uint2 g_agglo[N_NODES * 32];
__device__ uint2 g_xhi[N_NODES * 32];
__device__ uint2 g_xlo[N_NODES * 32];

// ---- bf16 split helpers: hi = truncate (exact bits), lo = rn(v-hi) ----
__device__ __forceinline__ uint32_t prmt_hi2(float v0, float v1) {
    uint32_t d;
    asm("prmt.b32 %0, %1, %2, 0x7632;"
        : "=r"(d) : "r"(__float_as_uint(v0)), "r"(__float_as_uint(v1)));
    return d;
}
__device__ __forceinline__ float trunc_hi(float v) {
    return __uint_as_float(__float_as_uint(v) & 0xFFFF0000u);
}
__device__ __forceinline__ uint32_t cvt2(float f0, float f1) {
    uint32_t d;
    asm("cvt.rn.bf16x2.f32 %0, %1, %2;" : "=r"(d) : "f"(f1), "f"(f0));
    return d;
}
__device__ __forceinline__ void split4(float4 v, uint2& hi, uint2& lo) {
    hi.x = prmt_hi2(v.x, v.y);
    hi.y = prmt_hi2(v.z, v.w);
    lo.x = cvt2(v.x - trunc_hi(v.x), v.y - trunc_hi(v.y));
    lo.y = cvt2(v.z - trunc_hi(v.z), v.w - trunc_hi(v.w));
}
// rn-rounded bf16x2 pair for the gather array (not the exact-split hi)
__device__ __forceinline__ uint2 rn4(float4 v) {
    uint2 r;
    r.x = cvt2(v.x, v.y);
    r.y = cvt2(v.z, v.w);
    return r;
}
__device__ __forceinline__ float4 bf4_to_f4(uint2 p) {
    float2 a = __bfloat1622float2(*(const __nv_bfloat162*)&p.x);
    float2 b = __bfloat1622float2(*(const __nv_bfloat162*)&p.y);
    return make_float4(a.x, a.y, b.x, b.y);
}

#define MMA16816(c, a0, a1, a2, a3, b0, b1) \
    asm volatile("mma.sync.aligned.m16n8k16.row.col.f32.bf16.bf16.f32 " \
                 "{%0,%1,%2,%3}, {%4,%5,%6,%7}, {%8,%9}, {%0,%1,%2,%3};" \
                 : "+f"((c)[0]), "+f"((c)[1]), "+f"((c)[2]), "+f"((c)[3]) \
                 : "r"(a0), "r"(a1), "r"(a2), "r"(a3), "r"(b0), "r"(b1))
#define LDSM4(r0, r1, r2, r3, addr) \
    asm volatile("ldmatrix.sync.aligned.m8n8.x4.shared.b16 {%0,%1,%2,%3}, [%4];" \
                 : "=r"(r0), "=r"(r1), "=r"(r2), "=r"(r3) : "r"(addr))
#define LDSM2(r0, r1, addr) \
    asm volatile("ldmatrix.sync.aligned.m8n8.x2.shared.b16 {%0,%1}, [%2];" \
                 : "=r"(r0), "=r"(r1) : "r"(addr))
#define CP16(dst, src, ssz) \
    asm volatile("cp.async.cg.shared.global [%0], [%1], 16, %2;" \
                 :: "r"(dst), "l"(src), "r"(ssz) : "memory")
#define CP_COMMIT() asm volatile("cp.async.commit_group;" ::: "memory")
#define CP_WAIT1()  asm volatile("cp.async.wait_group 1;" ::: "memory")

__device__ __forceinline__ uint32_t smem_u32(const void* p) {
    uint32_t a;
    asm("{ .reg .u64 t; cvta.to.shared.u64 t, %1; cvt.u32.u64 %0, t; }"
        : "=r"(a) : "l"(p));
    return a;
}

// ======================== graph preprocessing ==============================
__global__ void zero_kernel() {
    int idx = blockIdx.x * blockDim.x + threadIdx.x;
    int stride = gridDim.x * blockDim.x;
    for (int i = idx; i < N_NODES; i += stride) g_cnt[i] = 0;
}

__global__ void hist_kernel(const int* __restrict__ ei, int E) {
    int idx = blockIdx.x * blockDim.x + threadIdx.x;
    int stride = gridDim.x * blockDim.x;
    int E4 = E >> 2;
    const int4* d4 = (const int4*)(ei + E);
    for (int e = idx; e < E4; e += stride) {
        int4 d = d4[e];
        if ((unsigned)d.x < (unsigned)N_NODES) atomicAdd(&g_cnt[d.x], 1);
        if ((unsigned)d.y < (unsigned)N_NODES) atomicAdd(&g_cnt[d.y], 1);
        if ((unsigned)d.z < (unsigned)N_NODES) atomicAdd(&g_cnt[d.z], 1);
        if ((unsigned)d.w < (unsigned)N_NODES) atomicAdd(&g_cnt[d.w], 1);
    }
    // tail
    for (int e = (E4 << 2) + idx; e < E; e += stride) {
        int d = ei[E + e];
        if ((unsigned)d < (unsigned)N_NODES) atomicAdd(&g_cnt[d], 1);
    }
}

__global__ void scan1_kernel() {
    __shared__ int s[SCAN_BS];
    int tid = threadIdx.x;
    int i = blockIdx.x * SCAN_BS + tid;
    int v = (i < N_NODES) ? g_cnt[i] : 0;
    s[tid] = v;
    __syncthreads();
#pragma unroll
    for (int d = 1; d < SCAN_BS; d <<= 1) {
        int t = (tid >= d) ? s[tid - d] : 0;
        __syncthreads();
        s[tid] += t;
        __syncthreads();
    }
    if (i < N_NODES) g_off[i] = s[tid] - v;
    if (tid == SCAN_BS - 1) g_bsum[blockIdx.x] = s[tid];
}

// scan3 with fused scan2: each block reduces bsum[0..bid) itself
__global__ void scan3_kernel() {
    __shared__ int s[128];
    int bid = blockIdx.x;
    int tid = threadIdx.x;
    if (tid < 128) s[tid] = (tid < bid && tid < SCAN_NB) ? g_bsum[tid] : 0;
    __syncthreads();
#pragma unroll
    for (int d = 64; d > 0; d >>= 1) {
        if (tid < d) s[tid] += s[tid + d];
        __syncthreads();
    }
    int base = s[0];
    int i = bid * SCAN_BS + tid;
    if (i < N_NODES) {
        int off = g_off[i] + base;
        g_off[i] = off;
        g_cur[i] = off;   // cursor starts at absolute offset
    }
}

__global__ void fill_kernel(const int* __restrict__ ei, int E) {
    int idx = blockIdx.x * blockDim.x + threadIdx.x;
    int stride = gridDim.x * blockDim.x;
    int E4 = E >> 2;
    const int4* s4 = (const int4*)ei;
    const int4* d4 = (const int4*)(ei + E);
    for (int e = idx; e < E4; e += stride) {
        int4 s = s4[e];
        int4 d = d4[e];
        if ((unsigned)s.x < (unsigned)N_NODES && (unsigned)d.x < (unsigned)N_NODES)
            g_csr[atomicAdd(&g_cur[d.x], 1)] = s.x;
        if ((unsigned)s.y < (unsigned)N_NODES && (unsigned)d.y < (unsigned)N_NODES)
            g_csr[atomicAdd(&g_cur[d.y], 1)] = s.y;
        if ((unsigned)s.z < (unsigned)N_NODES && (unsigned)d.z < (unsigned)N_NODES)
            g_csr[atomicAdd(&g_cur[d.z], 1)] = s.z;
        if ((unsigned)s.w < (unsigned)N_NODES && (unsigned)d.w < (unsigned)N_NODES)
            g_csr[atomicAdd(&g_cur[d.w], 1)] = s.w;
    }
    for (int e = (E4 << 2) + idx; e < E; e += stride) {
        int s = ei[e];
        int d = ei[E + e];
        if ((unsigned)s < (unsigned)N_NODES && (unsigned)d < (unsigned)N_NODES)
            g_csr[atomicAdd(&g_cur[d], 1)] = s;
    }
}

// ---- x-convert: fp32 -> bf16 hi(rn-for-gather... hi must stay exact-split
// for the MMA path; gather uses the same hi (truncated) + we accept its error
// profile. Use exact split so transform semantics are identical to R9.
__global__ void xconv_kernel(const float* __restrict__ x) {
    int idx = blockIdx.x * blockDim.x + threadIdx.x;
    int stride = gridDim.x * blockDim.x;
    for (int i = idx; i < N_NODES * 32; i += stride) {
        float4 v = ((const float4*)x)[i];
        uint2 hi, lo;
        split4(v, hi, lo);
        g_xhi[i] = hi;
        g_xlo[i] = lo;
    }
}

// ---- aggregate: warp per node; gather bf16-hi rows (256B/edge) ----
__global__ void aggregate_kernel(const float* __restrict__ x) {
    int gtid = blockIdx.x * blockDim.x + threadIdx.x;
    int w = gtid >> 5;
    int lane = gtid & 31;
    if (w >= N_NODES) return;
    int off = g_off[w];
    int deg = g_cnt[w];
    int end = off + deg;

    float4 accA = make_float4(0.f, 0.f, 0.f, 0.f);
    float4 accB = make_float4(0.f, 0.f, 0.f, 0.f);
    int i = off;
    for (; i + 8 <= end; i += 8) {
        int s0 = g_csr[i+0], s1 = g_csr[i+1], s2 = g_csr[i+2], s3 = g_csr[i+3];
        int s4 = g_csr[i+4], s5 = g_csr[i+5], s6 = g_csr[i+6], s7 = g_csr[i+7];
        float4 v0 = bf4_to_f4(g_xhi[s0 * 32 + lane]);
        float4 v1 = bf4_to_f4(g_xhi[s1 * 32 + lane]);
        float4 v2 = bf4_to_f4(g_xhi[s2 * 32 + lane]);
        float4 v3 = bf4_to_f4(g_xhi[s3 * 32 + lane]);
        float4 v4 = bf4_to_f4(g_xhi[s4 * 32 + lane]);
        float4 v5 = bf4_to_f4(g_xhi[s5 * 32 + lane]);
        float4 v6 = bf4_to_f4(g_xhi[s6 * 32 + lane]);
        float4 v7 = bf4_to_f4(g_xhi[s7 * 32 + lane]);
        accA.x += (v0.x+v1.x)+(v2.x+v3.x); accA.y += (v0.y+v1.y)+(v2.y+v3.y);
        accA.z += (v0.z+v1.z)+(v2.z+v3.z); accA.w += (v0.w+v1.w)+(v2.w+v3.w);
        accB.x += (v4.x+v5.x)+(v6.x+v7.x); accB.y += (v4.y+v5.y)+(v6.y+v7.y);
        accB.z += (v4.z+v5.z)+(v6.z+v7.z); accB.w += (v4.w+v5.w)+(v6.w+v7.w);
    }
    for (; i < end; i++) {
        float4 v = bf4_to_f4(g_xhi[g_csr[i] * 32 + lane]);
        accA.x += v.x; accA.y += v.y; accA.z += v.z; accA.w += v.w;
    }
    float sc = 1.f / fmaxf((float)deg, 1.f);
    float4 o;
    o.x = (accA.x+accB.x)*sc; o.y = (accA.y+accB.y)*sc;
    o.z = (accA.z+accB.z)*sc; o.w = (accA.w+accB.w)*sc;
    uint2 hi, lo;
    split4(o, hi, lo);
    g_agghi[w * 32 + lane] = hi;
    g_agglo[w * 32 + lane] = lo;
}

// ===================== HMMA bf16x3 transform (pipelined) ===================
__device__ __forceinline__ void prefetch_A(uint32_t sbase, int bufbase,
                                           int tile, int tid) {
    int row0 = tile * TILE_M;
    int op = tid & 63;
    int a2 = op >> 4;          // 0 agghi, 1 xhi, 2 agglo, 3 xlo
    int u = op & 15;
    const char* arr;
    if (a2 == 0)      arr = (const char*)g_agghi;
    else if (a2 == 1) arr = (const char*)g_xhi;
    else if (a2 == 2) arr = (const char*)g_agglo;
    else              arr = (const char*)g_xlo;
    uint32_t dbase = sbase + bufbase + (a2 & 1) * 256 + (a2 >> 1) * ABUF_LO + u * 16;
    int rbase = tid >> 6;      // 0..3
#pragma unroll
    for (int i = 0; i < 8; i++) {
        int r = rbase + i * 4;
        int row = row0 + r;
        int ok = (row < N_NODES) ? 16 : 0;
        const char* src = arr + (long long)min(row, N_NODES - 1) * 256 + u * 16;
        CP16(dbase + r * LDAB, src, ok);
    }
}

__global__ void __launch_bounds__(256, 1)
transform_hmma(const float* __restrict__ W_l,
               const float* __restrict__ b_l,
               const float* __restrict__ W_r,
               float* __restrict__ out) {
    extern __shared__ char sm[];
    __shared__ float s_bias[128];

    int tid = threadIdx.x;
    int wid = tid >> 5;
    int lane = tid & 31;
    uint32_t sbase = smem_u32(sm);
    if (tid < 128) s_bias[tid] = b_l[tid];

    // B fill once: W -> bf16 hi/lo
    for (int idx = tid; idx < 128 * 64; idx += 256) {
        int n = idx >> 6;
        int kq = idx & 63;
        int k = kq * 4;
        const float* src = (k < 128) ? (W_l + n * 128 + k)
                                     : (W_r + n * 128 + (k - 128));
        float4 v = *(const float4*)src;
        uint2 hi, lo;
        split4(v, hi, lo);
        *(uint2*)(sm + OFF_BHI + n * LDAB + kq * 8) = hi;
        *(uint2*)(sm + OFF_BLO + n * LDAB + kq * 8) = lo;
    }

    int wr = (wid & 1) * 16;
    int nb = (wid >> 1) * 32;

    uint32_t aOff = (wr + (lane & 15)) * LDAB + ((lane >> 4) & 1) * 16;
    uint32_t bHi = sbase + OFF_BHI + (nb + (lane & 7)) * LDAB + ((lane >> 3) & 1) * 16;
    uint32_t bLo = bHi + (OFF_BLO - OFF_BHI);

    int tile = blockIdx.x;
    prefetch_A(sbase, 0, tile, tid);
    CP_COMMIT();

    int it = 0;
    for (; tile < NT2; tile += gridDim.x, it++) {
        int ntile = tile + gridDim.x;
        if (ntile < NT2) prefetch_A(sbase, ((it + 1) & 1) * ABUF_SZ, ntile, tid);
        CP_COMMIT();
        CP_WAIT1();
        __syncthreads();

        int row0 = tile * TILE_M;
        int g = lane >> 2;
        int tg = lane & 3;
        int r0 = row0 + wr + g;
        int r1 = r0 + 8;
        int c0 = g_cnt[r0];
        int c1 = g_cnt[r1];

        uint32_t abase = sbase + (it & 1) * ABUF_SZ;
        uint32_t aHi = abase + aOff;
        uint32_t aLo = aHi + ABUF_LO;

        float acc[4][4];
#pragma unroll
        for (int nt = 0; nt < 4; nt++)
#pragma unroll
            for (int j = 0; j < 4; j++) acc[nt][j] = 0.f;

#pragma unroll 2
        for (int ks = 0; ks < 16; ks++) {
            int kb = ks * 32;
            uint32_t a0, a1, a2, a3, l0, l1, l2, l3;
            LDSM4(a0, a1, a2, a3, aHi + kb);
            LDSM4(l0, l1, l2, l3, aLo + kb);
#pragma unroll
            for (int nt = 0; nt < 4; nt++) {
                uint32_t bh0, bh1, bl0, bl1;
                LDSM2(bh0, bh1, bHi + nt * 8 * LDAB + kb);
                LDSM2(bl0, bl1, bLo + nt * 8 * LDAB + kb);
                MMA16816(acc[nt], a0, a1, a2, a3, bh0, bh1);
                MMA16816(acc[nt], a0, a1, a2, a3, bl0, bl1);
                MMA16816(acc[nt], l0, l1, l2, l3, bh0, bh1);
            }
        }

        float df0 = (c0 > 0) ? 1.f : 0.f;
        float df1 = (c1 > 0) ? 1.f : 0.f;
#pragma unroll
        for (int nt = 0; nt < 4; nt++) {
            int col = nb + nt * 8 + tg * 2;
            float b0 = s_bias[col], b1 = s_bias[col + 1];
            float2 v0 = make_float2(acc[nt][0] + df0 * b0,
                                    acc[nt][1] + df0 * b1);
            *(float2*)(out + (long long)r0 * 128 + col) = v0;
            float2 v1 = make_float2(acc[nt][2] + df1 * b0,
                                    acc[nt][3] + df1 * b1);
            *(float2*)(out + (long long)r1 * 128 + col) = v1;
        }
        __syncthreads();
    }
}

// ---------------------------------------------------------------------------
// Launch
// ---------------------------------------------------------------------------
extern "C" void kernel_launch(void* const* d_in, const int* in_sizes, int n_in,
                              void* d_out, int out_size) {
    const float* x   = (const float*)d_in[0];
    const int*   ei  = (const int*)d_in[1];
    const float* W_l = (const float*)d_in[2];
    const float* b_l = (const float*)d_in[3];
    const float* W_r = (const float*)d_in[4];
    float*       out = (float*)d_out;
    int E = in_sizes[1] / 2;
    if (E > MAXE) E = MAXE;

    cudaFuncSetAttribute(transform_hmma,
                         cudaFuncAttributeMaxDynamicSharedMemorySize, SMEM_T);

    zero_kernel<<<256, 256>>>();
    hist_kernel<<<1024, 256>>>(ei, E);
    scan1_kernel<<<SCAN_NB, SCAN_BS>>>();
    scan3_kernel<<<SCAN_NB, SCAN_BS>>>();
    xconv_kernel<<<2048, 256>>>(x);
    fill_kernel<<<1024, 256>>>(ei, E);
    aggregate_kernel<<<(N_NODES * 32 + 255) / 256, 256>>>(x);
    transform_hmma<<<148, 256, SMEM_T>>>(W_l, b_l, W_r, out);
}

// round 11
// speedup vs baseline: 3.9081x; 1.0002x over previous
#include <cuda_runtime.h>
#include <cuda_bf16.h>
#include <cstdint>

#define N_NODES 100000
#define F 128
#define MAXE 1600000
#define SCAN_BS 1024
#define SCAN_NB ((N_NODES + SCAN_BS - 1) / SCAN_BS)   // 98

#define TILE_M 32
#define NT2 (N_NODES / TILE_M)                         // 3125 exact
#define LDAB 528                                       // 512B data + 16B pad
#define ABUF_LO 16896
#define ABUF_SZ 33792
#define OFF_BHI (2 * ABUF_SZ)                          // 67584
#define OFF_BLO (OFF_BHI + 128 * LDAB)                 // 135168
#define SMEM_T  (OFF_BLO + 128 * LDAB)                 // 202752

// Scratch (allocation-free rule: __device__ globals)
__device__ int   g_cnt[N_NODES];
__device__ int   g_cur[N_NODES];
__device__ int   g_off[N_NODES];
__device__ int   g_bsum[SCAN_NB + 1];
__device__ int   g_csr[MAXE];
// bf16 hi/lo packed: one uint2 = 4 bf16 (8B); 128 feats = 32 uint2 = 256B/row
__device__ uint2 g_agghi[N_NODES * 32];
__device__ uint2 g_agglo[N_NODES * 32];
__device__ uint2 g_xhi[N_NODES * 32];
__device__ uint2 g_xlo[N_NODES * 32];

// ---- bf16 rn split: hi = rn(v) (unbiased!), lo = rn(v - float(hi)) ----
__device__ __forceinline__ uint32_t cvt2(float f0, float f1) {
    uint32_t d;
    asm("cvt.rn.bf16x2.f32 %0, %1, %2;" : "=r"(d) : "f"(f1), "f"(f0));
    return d;
}
__device__ __forceinline__ float4 bf4_to_f4(uint2 p) {
    float2 a = __bfloat1622float2(*(const __nv_bfloat162*)&p.x);
    float2 b = __bfloat1622float2(*(const __nv_bfloat162*)&p.y);
    return make_float4(a.x, a.y, b.x, b.y);
}
__device__ __forceinline__ void split4(float4 v, uint2& hi, uint2& lo) {
    hi.x = cvt2(v.x, v.y);
    hi.y = cvt2(v.z, v.w);
    float4 h = bf4_to_f4(hi);
    lo.x = cvt2(v.x - h.x, v.y - h.y);
    lo.y = cvt2(v.z - h.z, v.w - h.w);
}

#define MMA16816(c, a0, a1, a2, a3, b0, b1) \
    asm volatile("mma.sync.aligned.m16n8k16.row.col.f32.bf16.bf16.f32 " \
                 "{%0,%1,%2,%3}, {%4,%5,%6,%7}, {%8,%9}, {%0,%1,%2,%3};" \
                 : "+f"((c)[0]), "+f"((c)[1]), "+f"((c)[2]), "+f"((c)[3]) \
                 : "r"(a0), "r"(a1), "r"(a2), "r"(a3), "r"(b0), "r"(b1))
#define LDSM4(r0, r1, r2, r3, addr) \
    asm volatile("ldmatrix.sync.aligned.m8n8.x4.shared.b16 {%0,%1,%2,%3}, [%4];" \
                 : "=r"(r0), "=r"(r1), "=r"(r2), "=r"(r3) : "r"(addr))
#define LDSM2(r0, r1, addr) \
    asm volatile("ldmatrix.sync.aligned.m8n8.x2.shared.b16 {%0,%1}, [%2];" \
                 : "=r"(r0), "=r"(r1) : "r"(addr))
#define CP16(dst, src, ssz) \
    asm volatile("cp.async.cg.shared.global [%0], [%1], 16, %2;" \
                 :: "r"(dst), "l"(src), "r"(ssz) : "memory")
#define CP_COMMIT() asm volatile("cp.async.commit_group;" ::: "memory")
#define CP_WAIT1()  asm volatile("cp.async.wait_group 1;" ::: "memory")

__device__ __forceinline__ uint32_t smem_u32(const void* p) {
    uint32_t a;
    asm("{ .reg .u64 t; cvta.to.shared.u64 t, %1; cvt.u32.u64 %0, t; }"
        : "=r"(a) : "l"(p));
    return a;
}

// ======================== graph preprocessing ==============================
__global__ void zero_kernel() {
    int idx = blockIdx.x * blockDim.x + threadIdx.x;
    int stride = gridDim.x * blockDim.x;
    for (int i = idx; i < N_NODES; i += stride) g_cnt[i] = 0;
}

// hist + fused x-convert (independent outputs, overlapped traffic)
__global__ void hist_xconv_kernel(const int* __restrict__ ei, int E,
                                  const float* __restrict__ x) {
    int idx = blockIdx.x * blockDim.x + threadIdx.x;
    int stride = gridDim.x * blockDim.x;
    // xconv part
    for (int i = idx; i < N_NODES * 32; i += stride) {
        float4 v = ((const float4*)x)[i];
        uint2 hi, lo;
        split4(v, hi, lo);
        g_xhi[i] = hi;
        g_xlo[i] = lo;
    }
    // hist part
    int E4 = E >> 2;
    const int4* d4 = (const int4*)(ei + E);
    for (int e = idx; e < E4; e += stride) {
        int4 d = d4[e];
        if ((unsigned)d.x < (unsigned)N_NODES) atomicAdd(&g_cnt[d.x], 1);
        if ((unsigned)d.y < (unsigned)N_NODES) atomicAdd(&g_cnt[d.y], 1);
        if ((unsigned)d.z < (unsigned)N_NODES) atomicAdd(&g_cnt[d.z], 1);
        if ((unsigned)d.w < (unsigned)N_NODES) atomicAdd(&g_cnt[d.w], 1);
    }
    for (int e = (E4 << 2) + idx; e < E; e += stride) {
        int d = ei[E + e];
        if ((unsigned)d < (unsigned)N_NODES) atomicAdd(&g_cnt[d], 1);
    }
}

__global__ void scan1_kernel() {
    __shared__ int s[SCAN_BS];
    int tid = threadIdx.x;
    int i = blockIdx.x * SCAN_BS + tid;
    int v = (i < N_NODES) ? g_cnt[i] : 0;
    s[tid] = v;
    __syncthreads();
#pragma unroll
    for (int d = 1; d < SCAN_BS; d <<= 1) {
        int t = (tid >= d) ? s[tid - d] : 0;
        __syncthreads();
        s[tid] += t;
        __syncthreads();
    }
    if (i < N_NODES) g_off[i] = s[tid] - v;
    if (tid == SCAN_BS - 1) g_bsum[blockIdx.x] = s[tid];
}

// scan3 with fused scan2: each block reduces bsum[0..bid) itself
__global__ void scan3_kernel() {
    __shared__ int s[128];
    int bid = blockIdx.x;
    int tid = threadIdx.x;
    if (tid < 128) s[tid] = (tid < bid && tid < SCAN_NB) ? g_bsum[tid] : 0;
    __syncthreads();
#pragma unroll
    for (int d = 64; d > 0; d >>= 1) {
        if (tid < d) s[tid] += s[tid + d];
        __syncthreads();
    }
    int base = s[0];
    int i = bid * SCAN_BS + tid;
    if (i < N_NODES) {
        int off = g_off[i] + base;
        g_off[i] = off;
        g_cur[i] = off;   // cursor starts at absolute offset
    }
}

__global__ void fill_kernel(const int* __restrict__ ei, int E) {
    int idx = blockIdx.x * blockDim.x + threadIdx.x;
    int stride = gridDim.x * blockDim.x;
    int E4 = E >> 2;
    const int4* s4 = (const int4*)ei;
    const int4* d4 = (const int4*)(ei + E);
    for (int e = idx; e < E4; e += stride) {
        int4 s = s4[e];
        int4 d = d4[e];
        if ((unsigned)s.x < (unsigned)N_NODES && (unsigned)d.x < (unsigned)N_NODES)
            g_csr[atomicAdd(&g_cur[d.x], 1)] = s.x;
        if ((unsigned)s.y < (unsigned)N_NODES && (unsigned)d.y < (unsigned)N_NODES)
            g_csr[atomicAdd(&g_cur[d.y], 1)] = s.y;
        if ((unsigned)s.z < (unsigned)N_NODES && (unsigned)d.z < (unsigned)N_NODES)
            g_csr[atomicAdd(&g_cur[d.z], 1)] = s.z;
        if ((unsigned)s.w < (unsigned)N_NODES && (unsigned)d.w < (unsigned)N_NODES)
            g_csr[atomicAdd(&g_cur[d.w], 1)] = s.w;
    }
    for (int e = (E4 << 2) + idx; e < E; e += stride) {
        int s = ei[e];
        int d = ei[E + e];
        if ((unsigned)s < (unsigned)N_NODES && (unsigned)d < (unsigned)N_NODES)
            g_csr[atomicAdd(&g_cur[d], 1)] = s;
    }
}

// ---- aggregate: warp per node; paired-lane bf16 gather (LDG.128) ----
// Half-warp h (lanes 0-15 / 16-31) handles alternating edges; each lane
// loads uint4 = 16B, 16 lanes cover the 256B row.
__global__ void aggregate_kernel() {
    int gtid = blockIdx.x * blockDim.x + threadIdx.x;
    int w = gtid >> 5;
    int lane = gtid & 31;
    if (w >= N_NODES) return;
    int off = g_off[w];
    int deg = g_cnt[w];
    int end = off + deg;

    int h = lane >> 4;         // half-warp id: 0 or 1
    int hl = lane & 15;        // lane within half: covers 16B*16 = 256B row
    const uint4* xh4 = (const uint4*)(const void*)g_xhi;

    // accumulate 8 floats per lane (two uint2 quads = 16B worth)
    float4 accA0 = make_float4(0.f,0.f,0.f,0.f), accA1 = accA0;
    float4 accB0 = accA0, accB1 = accA0;

    int i = off;
    for (; i + 8 <= end; i += 8) {
        int e0 = g_csr[i + h];
        int e1 = g_csr[i + 2 + h];
        int e2 = g_csr[i + 4 + h];
        int e3 = g_csr[i + 6 + h];
        uint4 p0 = xh4[e0 * 16 + hl];
        uint4 p1 = xh4[e1 * 16 + hl];
        uint4 p2 = xh4[e2 * 16 + hl];
        uint4 p3 = xh4[e3 * 16 + hl];
        float4 v;
        v = bf4_to_f4(make_uint2(p0.x, p0.y));
        accA0.x += v.x; accA0.y += v.y; accA0.z += v.z; accA0.w += v.w;
        v = bf4_to_f4(make_uint2(p0.z, p0.w));
        accA1.x += v.x; accA1.y += v.y; accA1.z += v.z; accA1.w += v.w;
        v = bf4_to_f4(make_uint2(p1.x, p1.y));
        accB0.x += v.x; accB0.y += v.y; accB0.z += v.z; accB0.w += v.w;
        v = bf4_to_f4(make_uint2(p1.z, p1.w));
        accB1.x += v.x; accB1.y += v.y; accB1.z += v.z; accB1.w += v.w;
        v = bf4_to_f4(make_uint2(p2.x, p2.y));
        accA0.x += v.x; accA0.y += v.y; accA0.z += v.z; accA0.w += v.w;
        v = bf4_to_f4(make_uint2(p2.z, p2.w));
        accA1.x += v.x; accA1.y += v.y; accA1.z += v.z; accA1.w += v.w;
        v = bf4_to_f4(make_uint2(p3.x, p3.y));
        accB0.x += v.x; accB0.y += v.y; accB0.z += v.z; accB0.w += v.w;
        v = bf4_to_f4(make_uint2(p3.z, p3.w));
        accB1.x += v.x; accB1.y += v.y; accB1.z += v.z; accB1.w += v.w;
    }
    // pair tail (2 edges per step)
    for (; i + 2 <= end; i += 2) {
        int e = g_csr[i + h];
        uint4 p = xh4[e * 16 + hl];
        float4 v = bf4_to_f4(make_uint2(p.x, p.y));
        accA0.x += v.x; accA0.y += v.y; accA0.z += v.z; accA0.w += v.w;
        v = bf4_to_f4(make_uint2(p.z, p.w));
        accA1.x += v.x; accA1.y += v.y; accA1.z += v.z; accA1.w += v.w;
    }
    // last odd edge: half 0 only
    if (i < end && h == 0) {
        int e = g_csr[i];
        uint4 p = xh4[e * 16 + hl];
        float4 v = bf4_to_f4(make_uint2(p.x, p.y));
        accA0.x += v.x; accA0.y += v.y; accA0.z += v.z; accA0.w += v.w;
        v = bf4_to_f4(make_uint2(p.z, p.w));
        accA1.x += v.x; accA1.y += v.y; accA1.z += v.z; accA1.w += v.w;
    }

    // combine halves: lane L needs partner lane L^16's accumulators
    float4 s0, s1;
    s0.x = accA0.x + accB0.x; s0.y = accA0.y + accB0.y;
    s0.z = accA0.z + accB0.z; s0.w = accA0.w + accB0.w;
    s1.x = accA1.x + accB1.x; s1.y = accA1.y + accB1.y;
    s1.z = accA1.z + accB1.z; s1.w = accA1.w + accB1.w;
    s0.x += __shfl_xor_sync(0xFFFFFFFF, s0.x, 16);
    s0.y += __shfl_xor_sync(0xFFFFFFFF, s0.y, 16);
    s0.z += __shfl_xor_sync(0xFFFFFFFF, s0.z, 16);
    s0.w += __shfl_xor_sync(0xFFFFFFFF, s0.w, 16);
    s1.x += __shfl_xor_sync(0xFFFFFFFF, s1.x, 16);
    s1.y += __shfl_xor_sync(0xFFFFFFFF, s1.y, 16);
    s1.z += __shfl_xor_sync(0xFFFFFFFF, s1.z, 16);
    s1.w += __shfl_xor_sync(0xFFFFFFFF, s1.w, 16);

    float sc = 1.f / fmaxf((float)deg, 1.f);
    s0.x *= sc; s0.y *= sc; s0.z *= sc; s0.w *= sc;
    s1.x *= sc; s1.y *= sc; s1.z *= sc; s1.w *= sc;

    // lane layout: halves hold duplicate sums; each half writes its 16B slot
    // row layout: quad q at uint2 index q; lane covers quads 2*hl+?:
    // uint4 index hl covers uint2 indices 2*hl, 2*hl+1 -> feats 8*hl..8*hl+7
    uint2 hi, lo;
    split4(s0, hi, lo);
    if (h == 0) {
        g_agghi[w * 32 + 2 * hl] = hi;
        g_agglo[w * 32 + 2 * hl] = lo;
    } else {
        split4(s1, hi, lo);
        g_agghi[w * 32 + 2 * hl + 1] = hi;
        g_agglo[w * 32 + 2 * hl + 1] = lo;
    }
    // the other quad from the opposite half:
    if (h == 0) {
        split4(s1, hi, lo);
        g_agghi[w * 32 + 2 * hl + 1] = hi;
        g_agglo[w * 32 + 2 * hl + 1] = lo;
    } else {
        split4(s0, hi, lo);
        g_agghi[w * 32 + 2 * hl] = hi;
        g_agglo[w * 32 + 2 * hl] = lo;
    }
}

// ===================== HMMA bf16x3 transform (pipelined) ===================
__device__ __forceinline__ void prefetch_A(uint32_t sbase, int bufbase,
                                           int tile, int tid) {
    int row0 = tile * TILE_M;
    int op = tid & 63;
    int a2 = op >> 4;          // 0 agghi, 1 xhi, 2 agglo, 3 xlo
    int u = op & 15;
    const char* arr;
    if (a2 == 0)      arr = (const char*)g_agghi;
    else if (a2 == 1) arr = (const char*)g_xhi;
    else if (a2 == 2) arr = (const char*)g_agglo;
    else              arr = (const char*)g_xlo;
    uint32_t dbase = sbase + bufbase + (a2 & 1) * 256 + (a2 >> 1) * ABUF_LO + u * 16;
    int rbase = tid >> 6;      // 0..3
#pragma unroll
    for (int i = 0; i < 8; i++) {
        int r = rbase + i * 4;
        int row = row0 + r;
        int ok = (row < N_NODES) ? 16 : 0;
        const char* src = arr + (long long)min(row, N_NODES - 1) * 256 + u * 16;
        CP16(dbase + r * LDAB, src, ok);
    }
}

__global__ void __launch_bounds__(256, 1)
transform_hmma(const float* __restrict__ W_l,
               const float* __restrict__ b_l,
               const float* __restrict__ W_r,
               float* __restrict__ out) {
    extern __shared__ char sm[];
    __shared__ float s_bias[128];

    int tid = threadIdx.x;
    int wid = tid >> 5;
    int lane = tid & 31;
    uint32_t sbase = smem_u32(sm);
    if (tid < 128) s_bias[tid] = b_l[tid];

    // B fill once: W -> bf16 hi/lo (rn split)
    for (int idx = tid; idx < 128 * 64; idx += 256) {
        int n = idx >> 6;
        int kq = idx & 63;
        int k = kq * 4;
        const float* src = (k < 128) ? (W_l + n * 128 + k)
                                     : (W_r + n * 128 + (k - 128));
        float4 v = *(const float4*)src;
        uint2 hi, lo;
        split4(v, hi, lo);
        *(uint2*)(sm + OFF_BHI + n * LDAB + kq * 8) = hi;
        *(uint2*)(sm + OFF_BLO + n * LDAB + kq * 8) = lo;
    }

    int wr = (wid & 1) * 16;
    int nb = (wid >> 1) * 32;

    uint32_t aOff = (wr + (lane & 15)) * LDAB + ((lane >> 4) & 1) * 16;
    uint32_t bHi = sbase + OFF_BHI + (nb + (lane & 7)) * LDAB + ((lane >> 3) & 1) * 16;
    uint32_t bLo = bHi + (OFF_BLO - OFF_BHI);

    int tile = blockIdx.x;
    prefetch_A(sbase, 0, tile, tid);
    CP_COMMIT();

    int it = 0;
    for (; tile < NT2; tile += gridDim.x, it++) {
        int ntile = tile + gridDim.x;
        if (ntile < NT2) prefetch_A(sbase, ((it + 1) & 1) * ABUF_SZ, ntile, tid);
        CP_COMMIT();
        CP_WAIT1();
        __syncthreads();

        int row0 = tile * TILE_M;
        int g = lane >> 2;
        int tg = lane & 3;
        int r0 = row0 + wr + g;
        int r1 = r0 + 8;
        int c0 = g_cnt[r0];
        int c1 = g_cnt[r1];

        uint32_t abase = sbase + (it & 1) * ABUF_SZ;
        uint32_t aHi = abase + aOff;
        uint32_t aLo = aHi + ABUF_LO;

        float acc[4][4];
#pragma unroll
        for (int nt = 0; nt < 4; nt++)
#pragma unroll
            for (int j = 0; j < 4; j++) acc[nt][j] = 0.f;

#pragma unroll 2
        for (int ks = 0; ks < 16; ks++) {
            int kb = ks * 32;
            uint32_t a0, a1, a2, a3, l0, l1, l2, l3;
            LDSM4(a0, a1, a2, a3, aHi + kb);
            LDSM4(l0, l1, l2, l3, aLo + kb);
#pragma unroll
            for (int nt = 0; nt < 4; nt++) {
                uint32_t bh0, bh1, bl0, bl1;
                LDSM2(bh0, bh1, bHi + nt * 8 * LDAB + kb);
                LDSM2(bl0, bl1, bLo + nt * 8 * LDAB + kb);
                MMA16816(acc[nt], a0, a1, a2, a3, bh0, bh1);
                MMA16816(acc[nt], a0, a1, a2, a3, bl0, bl1);
                MMA16816(acc[nt], l0, l1, l2, l3, bh0, bh1);
            }
        }

        float df0 = (c0 > 0) ? 1.f : 0.f;
        float df1 = (c1 > 0) ? 1.f : 0.f;
#pragma unroll
        for (int nt = 0; nt < 4; nt++) {
            int col = nb + nt * 8 + tg * 2;
            float b0 = s_bias[col], b1 = s_bias[col + 1];
            float2 v0 = make_float2(acc[nt][0] + df0 * b0,
                                    acc[nt][1] + df0 * b1);
            *(float2*)(out + (long long)r0 * 128 + col) = v0;
            float2 v1 = make_float2(acc[nt][2] + df1 * b0,
                                    acc[nt][3] + df1 * b1);
            *(float2*)(out + (long long)r1 * 128 + col) = v1;
        }
        __syncthreads();
    }
}

// ---------------------------------------------------------------------------
// Launch
// ---------------------------------------------------------------------------
extern "C" void kernel_launch(void* const* d_in, const int* in_sizes, int n_in,
                              void* d_out, int out_size) {
    const float* x   = (const float*)d_in[0];
    const int*   ei  = (const int*)d_in[1];
    const float* W_l = (const float*)d_in[2];
    const float* b_l = (const float*)d_in[3];
    const float* W_r = (const float*)d_in[4];
    float*       out = (float*)d_out;
    int E = in_sizes[1] / 2;
    if (E > MAXE) E = MAXE;

    cudaFuncSetAttribute(transform_hmma,
                         cudaFuncAttributeMaxDynamicSharedMemorySize, SMEM_T);

    zero_kernel<<<256, 256>>>();
    hist_xconv_kernel<<<2048, 256>>>(ei, E, x);
    scan1_kernel<<<SCAN_NB, SCAN_BS>>>();
    scan3_kernel<<<SCAN_NB, SCAN_BS>>>();
    fill_kernel<<<1024, 256>>>(ei, E);
    aggregate_kernel<<<(N_NODES * 32 + 255) / 256, 256>>>();
    transform_hmma<<<148, 256, SMEM_T>>>(W_l, b_l, W_r, out);
}